// round 10
// baseline (speedup 1.0000x reference)
#include <cuda_runtime.h>
#include <cstdint>
#include <math.h>

// AFMADEBlock: incremental triangular evaluation of the MADE autoregressive
// inverse. One degree-group finalized per step (31 steps).
//
// R10: serialization cuts on the R9 shape (net-split pairs, RPW=4, 256thr,
// grid 256, 16 warps/SM).
//  1. branch-free finalize (SEL + trash-slot stores) - no BSSY/BSYNC
//  2. 2-step weight phases: block barrier per PHASE (16 total), pair-scoped
//     bar.sync mid-phase for the emit exchange
//  3. outputs (y, logstd-sum) written once in an epilogue: col l is final
//     for all t >= l+1, so per-step stores/lssum bookkeeping are dead work.

#define Dd 32
#define Bb 4096
#define EPSf 1e-12f
#define RPW 4                  // rows per warp pair
#define NPAIR 4                // warp pairs per block
#define NWARP (2 * NPAIR)      // 8 warps
#define THREADS (NWARP * 32)   // 256
#define ROWS_PER_BLOCK (NPAIR * RPW)   // 16
#define GRID (Bb / ROWS_PER_BLOCK)     // 256

#define STEP_FLOATS 5696       // per-step staged weights (2 nets)
#define W1OFF 512
#define W2OFF 5120

// Permuted+masked weights (hidden units sorted by degree). ~656KB, static.
__device__ __align__(16) float g_W0p[2][32][256];
__device__ __align__(16) float g_W1p[2][256][256];
__device__ __align__(16) float g_W2p[2][256][32];
__device__ __align__(16) float g_b0p[2][256];
__device__ __align__(16) float g_b1p[2][256];
__device__ __align__(16) float g_b2[2][32];

// deg(i) = (i % 31) + 1 for original hidden index i.
// Sorted order: degrees 1..8 have 9 units, degrees 9..31 have 8 units.
__device__ __forceinline__ int degS(int k) {
    return (k < 72) ? (k / 9 + 1) : ((k - 72) / 8 + 9);
}
__device__ __forceinline__ int permS(int k) {
    int d, jj;
    if (k < 72) { d = k / 9 + 1;        jj = k % 9; }
    else        { d = (k - 72) / 8 + 9; jj = (k - 72) % 8; }
    return (d - 1) + 31 * jj;   // original index of k-th sorted unit
}

__global__ void prep_kernel(
    const float* __restrict__ mu_W0, const float* __restrict__ mu_b0,
    const float* __restrict__ mu_W1, const float* __restrict__ mu_b1,
    const float* __restrict__ mu_W2, const float* __restrict__ mu_b2,
    const float* __restrict__ lv_W0, const float* __restrict__ lv_b0,
    const float* __restrict__ lv_W1, const float* __restrict__ lv_b1,
    const float* __restrict__ lv_W2, const float* __restrict__ lv_b2)
{
    int idx = blockIdx.x * blockDim.x + threadIdx.x;
    if (idx >= 2 * 256 * 256) return;
    int net = idx >> 16;
    int k   = (idx >> 8) & 255;   // sorted hidden row
    int c   = idx & 255;          // sorted hidden col

    const float* W0 = net ? lv_W0 : mu_W0;
    const float* b0 = net ? lv_b0 : mu_b0;
    const float* W1 = net ? lv_W1 : mu_W1;
    const float* b1 = net ? lv_b1 : mu_b1;
    const float* W2 = net ? lv_W2 : mu_W2;
    const float* b2 = net ? lv_b2 : mu_b2;

    int dk = degS(k), pk = permS(k);
    int dc = degS(c), pc = permS(c);

    g_W1p[net][k][c] = (dc >= dk) ? W1[pk * 256 + pc] : 0.f;
    if (k < 32) g_W0p[net][k][c] = (dc >= (k + 1)) ? W0[k * 256 + pc] : 0.f;
    if (c < 32) g_W2p[net][k][c] = ((c + 1) > dk) ? W2[pk * 32 + c] : 0.f;
    if (k == 0) {
        g_b0p[net][c] = b0[pc];
        g_b1p[net][c] = b1[pc];
        if (c < 32) g_b2[net][c] = b2[c];
    }
}

__device__ __forceinline__ void cp16(void* s, const void* g) {
    unsigned int sa = (unsigned int)__cvta_generic_to_shared(s);
    asm volatile("cp.async.cg.shared.global [%0], [%1], 16;" :: "r"(sa), "l"(g));
}
__device__ __forceinline__ void cp_commit() {
    asm volatile("cp.async.commit_group;");
}
__device__ __forceinline__ void cp_wait_all() {
    asm volatile("cp.async.wait_group 0;");
}
__device__ __forceinline__ void pair_bar(int pair) {
    asm volatile("bar.sync %0, 64;" :: "r"(pair + 1) : "memory");
}

// Packed dual-fp32 FMA: d = a*b + d (elementwise on the two f32 halves).
__device__ __forceinline__ void ffma2(float2& d, const float2& a, const float2& b) {
    asm("fma.rn.f32x2 %0, %1, %2, %0;"
        : "+l"(reinterpret_cast<unsigned long long&>(d))
        : "l"(reinterpret_cast<const unsigned long long&>(a)),
          "l"(reinterpret_cast<const unsigned long long&>(b)));
}

// One degree-group step for ONE net over RPW=4 rows.
// Lane l owns cols 64e+2l+{0,1}, e in [E0,4). CNT = group size, E0 = off>>6.
// SB = smem base of this step's staged weights.
template<int CNT, int E0>
__device__ __forceinline__ void do_step(
    int l, int off, int net, const float2 y2[RPW],
    float2 a0[RPW][4], float2 a1[RPW][4], float2 aout2[2],
    const float* SB,
    float2 (*sH0)[RPW], float (*sH1)[RPW])
{
    const float* W0 = SB + net * 256;
    // ---- layer 0: a0 += y_j * W0row ----
#pragma unroll
    for (int e = E0; e < 4; e++) {
        float2 wv = *(const float2*)(W0 + 64 * e + 2 * l);
#pragma unroll
        for (int r = 0; r < RPW; r++) ffma2(a0[r][e], wv, y2[r]);
    }
    // finalize h0 group [off, off+CNT): branch-free, slot 15 = trash bin
#pragma unroll
    for (int e = E0; e < 4; e++) {
        int u0 = 64 * e + 2 * l - off;
        int i0 = ((unsigned)u0 < (unsigned)CNT) ? u0 : 15;
        int i1 = ((unsigned)(u0 + 1) < (unsigned)CNT) ? (u0 + 1) : 15;
#pragma unroll
        for (int r = 0; r < RPW; r++) {
            float h = fmaxf(a0[r][e].x, 0.f);
            sH0[i0][r] = make_float2(h, h);
        }
#pragma unroll
        for (int r = 0; r < RPW; r++) {
            float h = fmaxf(a0[r][e].y, 0.f);
            sH0[i1][r] = make_float2(h, h);
        }
    }
    __syncwarp();

    // ---- layer 1: a1 += h0_group @ W1 rows ----
#pragma unroll
    for (int u = 0; u < CNT; u++) {
        const float* wr = SB + W1OFF + (net * 9 + u) * 256;
        float2 wv[4];
#pragma unroll
        for (int e = E0; e < 4; e++)
            wv[e] = *(const float2*)(wr + 64 * e + 2 * l);
        float4 hq0 = *(const float4*)&sH0[u][0];  // {h0,h0,h1,h1}
        float4 hq1 = *(const float4*)&sH0[u][2];  // {h2,h2,h3,h3}
        float2 h0 = make_float2(hq0.x, hq0.y);
        float2 h1 = make_float2(hq0.z, hq0.w);
        float2 h2 = make_float2(hq1.x, hq1.y);
        float2 h3 = make_float2(hq1.z, hq1.w);
#pragma unroll
        for (int e = E0; e < 4; e++) {
            ffma2(a1[0][e], wv[e], h0);
            ffma2(a1[1][e], wv[e], h1);
            ffma2(a1[2][e], wv[e], h2);
            ffma2(a1[3][e], wv[e], h3);
        }
    }
    // finalize h1 group: branch-free scalar stores, slot 15 = trash
#pragma unroll
    for (int e = E0; e < 4; e++) {
        int u0 = 64 * e + 2 * l - off;
        int i0 = ((unsigned)u0 < (unsigned)CNT) ? u0 : 15;
        int i1 = ((unsigned)(u0 + 1) < (unsigned)CNT) ? (u0 + 1) : 15;
#pragma unroll
        for (int r = 0; r < RPW; r++)
            sH1[i0][r] = fmaxf(a1[r][e].x, 0.f);
#pragma unroll
        for (int r = 0; r < RPW; r++)
            sH1[i1][r] = fmaxf(a1[r][e].y, 0.f);
    }
    __syncwarp();

    // ---- layer 2: aout += h1_group @ W2 rows (row-pair packed) ----
#pragma unroll
    for (int u = 0; u < CNT; u++) {
        float wf = SB[W2OFF + (net * 9 + u) * 32 + l];
        float2 w2 = make_float2(wf, wf);
        float4 hA = *(const float4*)&sH1[u][0];   // rows 0..3
        ffma2(aout2[0], make_float2(hA.x, hA.y), w2);
        ffma2(aout2[1], make_float2(hA.z, hA.w), w2);
    }
}

// Prefetch weights for a step (row j, group offset off) into step base SB.
// Only alive columns [64*E0, 256) are fetched. Both nets staged.
template<int CNT, int E0>
__device__ __forceinline__ void prefetch_step(
    int j, int off, int tid, float* SB)
{
    constexpr int KC = 64 - 16 * E0;   // 16B chunks per W0/W1 row
#pragma unroll
    for (int net = 0; net < 2; net++) {
        if (tid < KC)
            cp16(SB + net * 256 + 64 * E0 + 4 * tid,
                 &g_W0p[net][j][64 * E0 + 4 * tid]);
        for (int i = tid; i < CNT * KC; i += THREADS) {
            int u = i / KC, q = i % KC;
            cp16(SB + W1OFF + (net * 9 + u) * 256 + 64 * E0 + 4 * q,
                 &g_W1p[net][off + u][64 * E0 + 4 * q]);
        }
        if (tid < CNT * 8) {
            int u = tid >> 3, q = tid & 7;
            cp16(SB + W2OFF + (net * 9 + u) * 32 + 4 * q,
                 &g_W2p[net][off + u][4 * q]);
        }
    }
}

__device__ __forceinline__ void dispatch_prefetch(int t, int tid, float* SB) {
    const int j = t - 1;
    const int off = (t <= 9) ? 9 * (t - 1) : 72 + 8 * (t - 9);
    if (t <= 8)       prefetch_step<9, 0>(j, off, tid, SB);
    else if (t <= 15) prefetch_step<8, 1>(j, off, tid, SB);
    else if (t <= 23) prefetch_step<8, 2>(j, off, tid, SB);
    else              prefetch_step<8, 3>(j, off, tid, SB);
}

__global__ __launch_bounds__(THREADS, 2)
void afmade_kernel(const float* __restrict__ x, float* __restrict__ out)
{
    // dynamic smem: 2 buffers x 2 step-slots x STEP_FLOATS
    extern __shared__ __align__(16) unsigned char dynsm[];
    float* SW = (float*)dynsm;

    __shared__ __align__(16) float2 sH0s[NWARP][16][RPW];  // per-warp h0 {h,h}, slot15=trash
    __shared__ __align__(16) float  sH1s[NWARP][16][RPW];  // per-warp h1 scalar, slot15=trash
    __shared__ __align__(16) float2 sD[2][NPAIR][2];       // (x - mu) row pairs (lane j)
    __shared__ __align__(16) float2 sI[2][NPAIR][2];       // 1/(exp(ls)+eps)   (lane j)
    __shared__ __align__(16) float  sIF[NPAIR][RPW][32];   // final inv, all cols

    const int tid  = threadIdx.x;
    const int w    = tid >> 5;
    const int l    = tid & 31;
    const int pair = w >> 1;
    const int net  = w & 1;          // 0 = mu, 1 = lv
    const int base_row = blockIdx.x * ROWS_PER_BLOCK + pair * RPW;

    float2 a0[RPW][4], a1[RPW][4], aout2[2];
    float2 xr2[2];

#pragma unroll
    for (int e = 0; e < 4; e++) {
        float2 b0v = *(const float2*)&g_b0p[net][64 * e + 2 * l];
        float2 b1v = *(const float2*)&g_b1p[net][64 * e + 2 * l];
#pragma unroll
        for (int r = 0; r < RPW; r++) { a0[r][e] = b0v; a1[r][e] = b1v; }
    }
    {
        float b2v = g_b2[net][l];
        aout2[0] = make_float2(b2v, b2v);
        aout2[1] = make_float2(b2v, b2v);
    }
#pragma unroll
    for (int rp = 0; rp < 2; rp++) {
        xr2[rp] = make_float2(x[(base_row + 2 * rp) * 32 + l],
                              x[(base_row + 2 * rp + 1) * 32 + l]);
    }

    // Prologue: stage phase 0 (steps 1 and 2) into buffer 0.
    prefetch_step<9, 0>(0, 0, tid, SW);                 // t=1 -> buf0 slot0
    prefetch_step<9, 0>(1, 9, tid, SW + STEP_FLOATS);   // t=2 -> buf0 slot1
    cp_commit();

    for (int t = 1; t <= 31; ++t) {
        const int j  = t - 1;
        const int tb = t & 1;
        // ---- emit: lane j publishes its net's contribution (uniform net branch)
        if (net == 0) {
            if (l == j) {
                sD[tb][pair][0] = make_float2(xr2[0].x - aout2[0].x,
                                              xr2[0].y - aout2[0].y);
                sD[tb][pair][1] = make_float2(xr2[1].x - aout2[1].x,
                                              xr2[1].y - aout2[1].y);
            }
        } else {
            float ls0 = 0.5f * aout2[0].x, ls1 = 0.5f * aout2[0].y;
            float ls2 = 0.5f * aout2[1].x, ls3 = 0.5f * aout2[1].y;
            float i0 = __fdividef(1.f, __expf(ls0) + EPSf);
            float i1 = __fdividef(1.f, __expf(ls1) + EPSf);
            float i2 = __fdividef(1.f, __expf(ls2) + EPSf);
            float i3 = __fdividef(1.f, __expf(ls3) + EPSf);
            if (l == j) {
                sI[tb][pair][0] = make_float2(i0, i1);
                sI[tb][pair][1] = make_float2(i2, i3);
            }
        }

        if (t & 1) {
            // phase boundary: weights for steps t, t+1 must be resident
            cp_wait_all();
            __syncthreads();
            if (t + 2 <= 31) {
                const int qn = (t + 1) >> 1;        // next phase index
                float* NB = SW + ((qn & 1) * 2) * STEP_FLOATS;
                dispatch_prefetch(t + 2, tid, NB);
                if (t + 3 <= 31)
                    dispatch_prefetch(t + 3, tid, NB + STEP_FLOATS);
                cp_commit();
            }
        } else {
            pair_bar(pair);   // orders mid-phase exchange within the pair
        }

        // ---- everyone builds y for the 4 rows (broadcast LDS reads) ----
        float2 y2[RPW];
        {
            float4 d0 = *(const float4*)&sD[tb][pair][0];
            float4 i0 = *(const float4*)&sI[tb][pair][0];
            float yv[RPW] = {d0.x * i0.x, d0.y * i0.y, d0.z * i0.z, d0.w * i0.w};
#pragma unroll
            for (int r = 0; r < RPW; r++) y2[r] = make_float2(yv[r], yv[r]);
        }

        const int off = (t <= 9) ? 9 * (t - 1) : 72 + 8 * (t - 9);
        const float* SB = SW + ((((t - 1) >> 1) & 1) * 2 + ((t - 1) & 1)) * STEP_FLOATS;
        if (t <= 8)
            do_step<9, 0>(l, off, net, y2, a0, a1, aout2, SB, sH0s[w], sH1s[w]);
        else if (t <= 15)
            do_step<8, 1>(l, off, net, y2, a0, a1, aout2, SB, sH0s[w], sH1s[w]);
        else if (t <= 23)
            do_step<8, 2>(l, off, net, y2, a0, a1, aout2, SB, sH0s[w], sH1s[w]);
        else
            do_step<8, 3>(l, off, net, y2, a0, a1, aout2, SB, sH0s[w], sH1s[w]);
    }

    // ---- epilogue (t = 32): every col is final now ----
    if (net == 1) {
        // lv-warp: publish inv for all cols, keep ls for the row-sum
        float ls[RPW] = {0.5f * aout2[0].x, 0.5f * aout2[0].y,
                         0.5f * aout2[1].x, 0.5f * aout2[1].y};
#pragma unroll
        for (int r = 0; r < RPW; r++)
            sIF[pair][r][l] = __fdividef(1.f, __expf(ls[r]) + EPSf);
        pair_bar(pair);
        // logstd row-sums: reduce lane-held ls over lanes
#pragma unroll
        for (int r = 0; r < RPW; r++) {
            float s = ls[r];
#pragma unroll
            for (int o = 16; o > 0; o >>= 1) s += __shfl_xor_sync(0xffffffffu, s, o);
            if (l == 0) out[Bb * Dd + base_row + r] = s;
        }
    } else {
        float d[RPW] = {xr2[0].x - aout2[0].x, xr2[0].y - aout2[0].y,
                        xr2[1].x - aout2[1].x, xr2[1].y - aout2[1].y};
        pair_bar(pair);
#pragma unroll
        for (int r = 0; r < RPW; r++)
            out[(base_row + r) * 32 + l] = d[r] * sIF[pair][r][l];
    }
}

extern "C" void kernel_launch(void* const* d_in, const int* in_sizes, int n_in,
                              void* d_out, int out_size)
{
    (void)in_sizes; (void)n_in; (void)out_size;
    const float* x = (const float*)d_in[0];

    prep_kernel<<<512, 256>>>(
        (const float*)d_in[1],  (const float*)d_in[2],  (const float*)d_in[3],
        (const float*)d_in[4],  (const float*)d_in[5],  (const float*)d_in[6],
        (const float*)d_in[7],  (const float*)d_in[8],  (const float*)d_in[9],
        (const float*)d_in[10], (const float*)d_in[11], (const float*)d_in[12]);

    const int dyn_smem = 4 * STEP_FLOATS * 4;   // 91136 B (2 buffers x 2 steps)
    cudaFuncSetAttribute(afmade_kernel,
                         cudaFuncAttributeMaxDynamicSharedMemorySize, dyn_smem);
    afmade_kernel<<<GRID, THREADS, dyn_smem>>>(x, (float*)d_out);
}

// round 11
// speedup vs baseline: 1.1979x; 1.1979x over previous
#include <cuda_runtime.h>
#include <cstdint>
#include <math.h>

// AFMADEBlock: incremental triangular evaluation of the MADE autoregressive
// inverse. One degree-group finalized per step (31 steps).
//
// R11 = R5 (best, 52.0us) + 4-slot staging ring. Weights for 2 steps staged
// per phase; block barrier only at phase boundaries (31 -> 16 barriers).
// Warps are fully autonomous within a phase (emit via shfl, h-exchange is
// per-warp) -> crossbar bursts decorrelate, barrier-convoy cost halves.
// Body/emit/finalize identical to R5.

#define Dd 32
#define Bb 4096
#define EPSf 1e-12f
#define RPW 4                  // rows per warp
#define NWARP 4                // warps per block
#define THREADS (NWARP * 32)   // 128
#define ROWS_PER_BLOCK (NWARP * RPW)   // 16
#define GRID (Bb / ROWS_PER_BLOCK)     // 256

#define STEP_FLOATS 5696       // per-step staged weights (2 nets)
#define W1OFF 512
#define W2OFF 5120

// Permuted+masked weights (hidden units sorted by degree). ~656KB, static.
__device__ __align__(16) float g_W0p[2][32][256];
__device__ __align__(16) float g_W1p[2][256][256];
__device__ __align__(16) float g_W2p[2][256][32];
__device__ __align__(16) float g_b0p[2][256];
__device__ __align__(16) float g_b1p[2][256];
__device__ __align__(16) float g_b2[2][32];

// deg(i) = (i % 31) + 1 for original hidden index i.
// Sorted order: degrees 1..8 have 9 units, degrees 9..31 have 8 units.
__device__ __forceinline__ int degS(int k) {
    return (k < 72) ? (k / 9 + 1) : ((k - 72) / 8 + 9);
}
__device__ __forceinline__ int permS(int k) {
    int d, jj;
    if (k < 72) { d = k / 9 + 1;        jj = k % 9; }
    else        { d = (k - 72) / 8 + 9; jj = (k - 72) % 8; }
    return (d - 1) + 31 * jj;   // original index of k-th sorted unit
}

__global__ void prep_kernel(
    const float* __restrict__ mu_W0, const float* __restrict__ mu_b0,
    const float* __restrict__ mu_W1, const float* __restrict__ mu_b1,
    const float* __restrict__ mu_W2, const float* __restrict__ mu_b2,
    const float* __restrict__ lv_W0, const float* __restrict__ lv_b0,
    const float* __restrict__ lv_W1, const float* __restrict__ lv_b1,
    const float* __restrict__ lv_W2, const float* __restrict__ lv_b2)
{
    int idx = blockIdx.x * blockDim.x + threadIdx.x;
    if (idx >= 2 * 256 * 256) return;
    int net = idx >> 16;
    int k   = (idx >> 8) & 255;   // sorted hidden row
    int c   = idx & 255;          // sorted hidden col

    const float* W0 = net ? lv_W0 : mu_W0;
    const float* b0 = net ? lv_b0 : mu_b0;
    const float* W1 = net ? lv_W1 : mu_W1;
    const float* b1 = net ? lv_b1 : mu_b1;
    const float* W2 = net ? lv_W2 : mu_W2;
    const float* b2 = net ? lv_b2 : mu_b2;

    int dk = degS(k), pk = permS(k);
    int dc = degS(c), pc = permS(c);

    g_W1p[net][k][c] = (dc >= dk) ? W1[pk * 256 + pc] : 0.f;
    if (k < 32) g_W0p[net][k][c] = (dc >= (k + 1)) ? W0[k * 256 + pc] : 0.f;
    if (c < 32) g_W2p[net][k][c] = ((c + 1) > dk) ? W2[pk * 32 + c] : 0.f;
    if (k == 0) {
        g_b0p[net][c] = b0[pc];
        g_b1p[net][c] = b1[pc];
        if (c < 32) g_b2[net][c] = b2[c];
    }
}

__device__ __forceinline__ void cp16(void* s, const void* g) {
    unsigned int sa = (unsigned int)__cvta_generic_to_shared(s);
    asm volatile("cp.async.cg.shared.global [%0], [%1], 16;" :: "r"(sa), "l"(g));
}
__device__ __forceinline__ void cp_commit() {
    asm volatile("cp.async.commit_group;");
}
__device__ __forceinline__ void cp_wait_all() {
    asm volatile("cp.async.wait_group 0;");
}

// Packed dual-fp32 FMA: d = a*b + d (elementwise on the two f32 halves).
__device__ __forceinline__ void ffma2(float2& d, const float2& a, const float2& b) {
    asm("fma.rn.f32x2 %0, %1, %2, %0;"
        : "+l"(reinterpret_cast<unsigned long long&>(d))
        : "l"(reinterpret_cast<const unsigned long long&>(a)),
          "l"(reinterpret_cast<const unsigned long long&>(b)));
}

// One degree-group step (both nets, RPW=4 rows). Identical to R5's body;
// weights addressed from the flat step slot SB.
// Lane l owns cols 64e+2l+{0,1}, e in [E0,4). CNT = group size, E0 = off>>6.
template<int CNT, int E0>
__device__ __forceinline__ void do_step(
    int l, int off, const float2 y2[RPW],
    float2 a0[2][RPW][4], float2 a1[2][RPW][4], float2 aout2[2][2],
    const float* SB,
    float2 (*sH0)[9][RPW], float2 (*sH1)[9][2])
{
    // ---- layer 0: a0 += y_j * W0row ----
#pragma unroll
    for (int net = 0; net < 2; net++) {
#pragma unroll
        for (int e = E0; e < 4; e++) {
            float2 wv = *(const float2*)(SB + net * 256 + 64 * e + 2 * l);
#pragma unroll
            for (int r = 0; r < RPW; r++) ffma2(a0[net][r][e], wv, y2[r]);
        }
    }
    // finalize h0 group [off, off+CNT) -> sH0[net][u][r] = {h,h}
#pragma unroll
    for (int net = 0; net < 2; net++) {
#pragma unroll
        for (int e = E0; e < 4; e++) {
            int u0 = 64 * e + 2 * l - off;
            if (u0 >= 0 && u0 < CNT) {
#pragma unroll
                for (int r = 0; r < RPW; r++) {
                    float h = fmaxf(a0[net][r][e].x, 0.f);
                    sH0[net][u0][r] = make_float2(h, h);
                }
            }
            if (u0 + 1 >= 0 && u0 + 1 < CNT) {
#pragma unroll
                for (int r = 0; r < RPW; r++) {
                    float h = fmaxf(a0[net][r][e].y, 0.f);
                    sH0[net][u0 + 1][r] = make_float2(h, h);
                }
            }
        }
    }
    __syncwarp();

    // ---- layer 1: a1 += h0_group @ W1 rows ----
#pragma unroll
    for (int u = 0; u < CNT; u++) {
#pragma unroll
        for (int net = 0; net < 2; net++) {
            const float* wr = SB + W1OFF + (net * 9 + u) * 256;
            float2 wv[4];
#pragma unroll
            for (int e = E0; e < 4; e++)
                wv[e] = *(const float2*)(wr + 64 * e + 2 * l);
            float4 hq0 = *(const float4*)&sH0[net][u][0];  // {h0,h0,h1,h1}
            float4 hq1 = *(const float4*)&sH0[net][u][2];  // {h2,h2,h3,h3}
            float2 h0 = make_float2(hq0.x, hq0.y);
            float2 h1 = make_float2(hq0.z, hq0.w);
            float2 h2 = make_float2(hq1.x, hq1.y);
            float2 h3 = make_float2(hq1.z, hq1.w);
#pragma unroll
            for (int e = E0; e < 4; e++) {
                ffma2(a1[0 * 0 + net][0][e], wv[e], h0);   // net index explicit below
            }
            // (expanded per-row to keep ptxas from reordering into spills)
#pragma unroll
            for (int e = E0; e < 4; e++) {
                ffma2(a1[net][1][e], wv[e], h1);
                ffma2(a1[net][2][e], wv[e], h2);
                ffma2(a1[net][3][e], wv[e], h3);
            }
        }
    }
    // finalize h1 group -> sH1[net][u][rp] = {h(2rp), h(2rp+1)}
#pragma unroll
    for (int net = 0; net < 2; net++) {
#pragma unroll
        for (int e = E0; e < 4; e++) {
            int u0 = 64 * e + 2 * l - off;
            if (u0 >= 0 && u0 < CNT) {
#pragma unroll
                for (int rp = 0; rp < 2; rp++)
                    sH1[net][u0][rp] = make_float2(
                        fmaxf(a1[net][2 * rp][e].x, 0.f),
                        fmaxf(a1[net][2 * rp + 1][e].x, 0.f));
            }
            if (u0 + 1 >= 0 && u0 + 1 < CNT) {
#pragma unroll
                for (int rp = 0; rp < 2; rp++)
                    sH1[net][u0 + 1][rp] = make_float2(
                        fmaxf(a1[net][2 * rp][e].y, 0.f),
                        fmaxf(a1[net][2 * rp + 1][e].y, 0.f));
            }
        }
    }
    __syncwarp();

    // ---- layer 2: aout += h1_group @ W2 rows (row-pair packed) ----
#pragma unroll
    for (int u = 0; u < CNT; u++) {
#pragma unroll
        for (int net = 0; net < 2; net++) {
            float wf = SB[W2OFF + (net * 9 + u) * 32 + l];
            float2 w2 = make_float2(wf, wf);
#pragma unroll
            for (int rp = 0; rp < 2; rp++) {
                float2 h2 = sH1[net][u][rp];
                ffma2(aout2[net][rp], h2, w2);
            }
        }
    }
}

// Prefetch weights for a step (row j, group offset off) into step slot SB.
// Only alive columns [64*E0, 256) are fetched. Both nets staged.
template<int CNT, int E0>
__device__ __forceinline__ void prefetch_step(
    int j, int off, int tid, float* SB)
{
    constexpr int KC = 64 - 16 * E0;   // 16B chunks per W0/W1 row
#pragma unroll
    for (int net = 0; net < 2; net++) {
        if (tid < KC)
            cp16(SB + net * 256 + 64 * E0 + 4 * tid,
                 &g_W0p[net][j][64 * E0 + 4 * tid]);
        for (int i = tid; i < CNT * KC; i += THREADS) {
            int u = i / KC, q = i % KC;
            cp16(SB + W1OFF + (net * 9 + u) * 256 + 64 * E0 + 4 * q,
                 &g_W1p[net][off + u][64 * E0 + 4 * q]);
        }
        if (tid < CNT * 8) {
            int u = tid >> 3, q = tid & 7;
            cp16(SB + W2OFF + (net * 9 + u) * 32 + 4 * q,
                 &g_W2p[net][off + u][4 * q]);
        }
    }
}

__device__ __forceinline__ void dispatch_prefetch(int t, int tid, float* SB) {
    const int j = t - 1;
    const int off = (t <= 9) ? 9 * (t - 1) : 72 + 8 * (t - 9);
    if (t <= 8)       prefetch_step<9, 0>(j, off, tid, SB);
    else if (t <= 15) prefetch_step<8, 1>(j, off, tid, SB);
    else if (t <= 23) prefetch_step<8, 2>(j, off, tid, SB);
    else              prefetch_step<8, 3>(j, off, tid, SB);
}

__global__ __launch_bounds__(THREADS, 2)
void afmade_kernel(const float* __restrict__ x, float* __restrict__ out)
{
    // dynamic smem: 4 step slots (2 phases x 2 steps) x STEP_FLOATS
    extern __shared__ __align__(16) unsigned char dynsm[];
    float* SW = (float*)dynsm;

    __shared__ __align__(16) float2 sH0s[NWARP][2][9][RPW];  // per-warp h0 {h,h}
    __shared__ __align__(16) float2 sH1s[NWARP][2][9][2];    // per-warp h1 row pairs

    const int tid = threadIdx.x;
    const int w   = tid >> 5;
    const int l   = tid & 31;
    const int base_row = (blockIdx.x * NWARP + w) * RPW;

    float2 a0[2][RPW][4], a1[2][RPW][4], aout2[2][2];
    float2 xr2[2], lssum2[2];

#pragma unroll
    for (int net = 0; net < 2; net++) {
#pragma unroll
        for (int e = 0; e < 4; e++) {
            float2 b0v = *(const float2*)&g_b0p[net][64 * e + 2 * l];
            float2 b1v = *(const float2*)&g_b1p[net][64 * e + 2 * l];
#pragma unroll
            for (int r = 0; r < RPW; r++) { a0[net][r][e] = b0v; a1[net][r][e] = b1v; }
        }
        float b2v = g_b2[net][l];
        aout2[net][0] = make_float2(b2v, b2v);
        aout2[net][1] = make_float2(b2v, b2v);
    }
#pragma unroll
    for (int rp = 0; rp < 2; rp++) {
        lssum2[rp] = make_float2(0.f, 0.f);
        xr2[rp] = make_float2(x[(base_row + 2 * rp) * 32 + l],
                              x[(base_row + 2 * rp + 1) * 32 + l]);
    }

    // Prologue: stage phase 0 (steps 1, 2) into slots 0, 1.
    prefetch_step<9, 0>(0, 0, tid, SW);                 // t=1 -> slot 0
    prefetch_step<9, 0>(1, 9, tid, SW + STEP_FLOATS);   // t=2 -> slot 1
    cp_commit();

    for (int t = 1; t <= 32; ++t) {
        const int j = t - 1;
        // ---- emit coordinate j (registers + shfl only, R5 style) ----
        float2 y2[RPW];
#pragma unroll
        for (int rp = 0; rp < 2; rp++) {
            float mu0 = aout2[0][rp].x, mu1 = aout2[0][rp].y;
            float lv0 = aout2[1][rp].x, lv1 = aout2[1][rp].y;
            float ls0 = 0.5f * lv0, ls1 = 0.5f * lv1;
            float yc0 = __fdividef(xr2[rp].x - mu0, __expf(ls0) + EPSf);
            float yc1 = __fdividef(xr2[rp].y - mu1, __expf(ls1) + EPSf);
            if (l == j) {
                lssum2[rp].x += ls0;
                lssum2[rp].y += ls1;
                out[(base_row + 2 * rp) * 32 + j]     = yc0;
                out[(base_row + 2 * rp + 1) * 32 + j] = yc1;
            }
            float yv0 = __shfl_sync(0xffffffffu, yc0, j);
            float yv1 = __shfl_sync(0xffffffffu, yc1, j);
            y2[2 * rp]     = make_float2(yv0, yv0);
            y2[2 * rp + 1] = make_float2(yv1, yv1);
        }
        if (t == 32) break;

        if (t & 1) {
            // Phase boundary: weights for steps t, t+1 must be resident.
            cp_wait_all();
            __syncthreads();
            // Prefetch next phase into the slots freed by the previous one.
            if (t + 2 <= 31) {
                const int pn = (t + 1) >> 1;   // next phase index
                float* NB = SW + ((pn & 1) * 2) * STEP_FLOATS;
                dispatch_prefetch(t + 2, tid, NB);
                if (t + 3 <= 31)
                    dispatch_prefetch(t + 3, tid, NB + STEP_FLOATS);
                cp_commit();
            }
        }
        // even t: no cross-warp sync at all — warps free-run within the phase

        const int off = (t <= 9) ? 9 * (t - 1) : 72 + 8 * (t - 9);
        const float* SB = SW + ((((t - 1) >> 1) & 1) * 2 + ((t - 1) & 1)) * STEP_FLOATS;
        if (t <= 8)
            do_step<9, 0>(l, off, y2, a0, a1, aout2, SB, sH0s[w], sH1s[w]);
        else if (t <= 15)
            do_step<8, 1>(l, off, y2, a0, a1, aout2, SB, sH0s[w], sH1s[w]);
        else if (t <= 23)
            do_step<8, 2>(l, off, y2, a0, a1, aout2, SB, sH0s[w], sH1s[w]);
        else
            do_step<8, 3>(l, off, y2, a0, a1, aout2, SB, sH0s[w], sH1s[w]);
    }

    // ---- logstd row-sums (lane l holds coordinate l's contribution) ----
#pragma unroll
    for (int rp = 0; rp < 2; rp++) {
        float sx = lssum2[rp].x, sy = lssum2[rp].y;
#pragma unroll
        for (int o = 16; o > 0; o >>= 1) {
            sx += __shfl_xor_sync(0xffffffffu, sx, o);
            sy += __shfl_xor_sync(0xffffffffu, sy, o);
        }
        if (l == 0) {
            out[Bb * Dd + base_row + 2 * rp]     = sx;
            out[Bb * Dd + base_row + 2 * rp + 1] = sy;
        }
    }
}

extern "C" void kernel_launch(void* const* d_in, const int* in_sizes, int n_in,
                              void* d_out, int out_size)
{
    (void)in_sizes; (void)n_in; (void)out_size;
    const float* x = (const float*)d_in[0];

    prep_kernel<<<512, 256>>>(
        (const float*)d_in[1],  (const float*)d_in[2],  (const float*)d_in[3],
        (const float*)d_in[4],  (const float*)d_in[5],  (const float*)d_in[6],
        (const float*)d_in[7],  (const float*)d_in[8],  (const float*)d_in[9],
        (const float*)d_in[10], (const float*)d_in[11], (const float*)d_in[12]);

    const int dyn_smem = 4 * STEP_FLOATS * 4;   // 91136 B (4 step slots)
    cudaFuncSetAttribute(afmade_kernel,
                         cudaFuncAttributeMaxDynamicSharedMemorySize, dyn_smem);
    afmade_kernel<<<GRID, THREADS, dyn_smem>>>(x, (float*)d_out);
}

// round 12
// speedup vs baseline: 1.2733x; 1.0629x over previous
#include <cuda_runtime.h>
#include <cstdint>
#include <math.h>

// AFMADEBlock: incremental triangular evaluation of the MADE autoregressive
// inverse. One degree-group finalized per step (31 steps).
//
// R12 = R11 + instruction diet:
//  (a) warp-structured prefetch: no integer div/mod by KC (was ~90 alu
//      instr/thread/step of address math; alu pipe was 22.4%)
//  (b) emit via (x-mu)*exp(-ls) instead of fdividef(.., exp(ls)+EPS):
//      EPS contributes <=2e-11 rel; saves RCP (16cyc) on the serial chain
//  Shape unchanged: RPW=4 both nets, 128thr, grid 256, 4-slot staging ring,
//  phase barriers (16), dead-block skip, fma.rn.f32x2.

#define Dd 32
#define Bb 4096
#define RPW 4                  // rows per warp
#define NWARP 4                // warps per block
#define THREADS (NWARP * 32)   // 128
#define ROWS_PER_BLOCK (NWARP * RPW)   // 16
#define GRID (Bb / ROWS_PER_BLOCK)     // 256

#define STEP_FLOATS 5696       // per-step staged weights (2 nets)
#define W1OFF 512
#define W2OFF 5120

// Permuted+masked weights (hidden units sorted by degree). ~656KB, static.
__device__ __align__(16) float g_W0p[2][32][256];
__device__ __align__(16) float g_W1p[2][256][256];
__device__ __align__(16) float g_W2p[2][256][32];
__device__ __align__(16) float g_b0p[2][256];
__device__ __align__(16) float g_b1p[2][256];
__device__ __align__(16) float g_b2[2][32];

// deg(i) = (i % 31) + 1 for original hidden index i.
// Sorted order: degrees 1..8 have 9 units, degrees 9..31 have 8 units.
__device__ __forceinline__ int degS(int k) {
    return (k < 72) ? (k / 9 + 1) : ((k - 72) / 8 + 9);
}
__device__ __forceinline__ int permS(int k) {
    int d, jj;
    if (k < 72) { d = k / 9 + 1;        jj = k % 9; }
    else        { d = (k - 72) / 8 + 9; jj = (k - 72) % 8; }
    return (d - 1) + 31 * jj;   // original index of k-th sorted unit
}

__global__ void prep_kernel(
    const float* __restrict__ mu_W0, const float* __restrict__ mu_b0,
    const float* __restrict__ mu_W1, const float* __restrict__ mu_b1,
    const float* __restrict__ mu_W2, const float* __restrict__ mu_b2,
    const float* __restrict__ lv_W0, const float* __restrict__ lv_b0,
    const float* __restrict__ lv_W1, const float* __restrict__ lv_b1,
    const float* __restrict__ lv_W2, const float* __restrict__ lv_b2)
{
    int idx = blockIdx.x * blockDim.x + threadIdx.x;
    if (idx >= 2 * 256 * 256) return;
    int net = idx >> 16;
    int k   = (idx >> 8) & 255;   // sorted hidden row
    int c   = idx & 255;          // sorted hidden col

    const float* W0 = net ? lv_W0 : mu_W0;
    const float* b0 = net ? lv_b0 : mu_b0;
    const float* W1 = net ? lv_W1 : mu_W1;
    const float* b1 = net ? lv_b1 : mu_b1;
    const float* W2 = net ? lv_W2 : mu_W2;
    const float* b2 = net ? lv_b2 : mu_b2;

    int dk = degS(k), pk = permS(k);
    int dc = degS(c), pc = permS(c);

    g_W1p[net][k][c] = (dc >= dk) ? W1[pk * 256 + pc] : 0.f;
    if (k < 32) g_W0p[net][k][c] = (dc >= (k + 1)) ? W0[k * 256 + pc] : 0.f;
    if (c < 32) g_W2p[net][k][c] = ((c + 1) > dk) ? W2[pk * 32 + c] : 0.f;
    if (k == 0) {
        g_b0p[net][c] = b0[pc];
        g_b1p[net][c] = b1[pc];
        if (c < 32) g_b2[net][c] = b2[c];
    }
}

__device__ __forceinline__ void cp16(void* s, const void* g) {
    unsigned int sa = (unsigned int)__cvta_generic_to_shared(s);
    asm volatile("cp.async.cg.shared.global [%0], [%1], 16;" :: "r"(sa), "l"(g));
}
__device__ __forceinline__ void cp_commit() {
    asm volatile("cp.async.commit_group;");
}
__device__ __forceinline__ void cp_wait_all() {
    asm volatile("cp.async.wait_group 0;");
}

// Packed dual-fp32 FMA: d = a*b + d (elementwise on the two f32 halves).
__device__ __forceinline__ void ffma2(float2& d, const float2& a, const float2& b) {
    asm("fma.rn.f32x2 %0, %1, %2, %0;"
        : "+l"(reinterpret_cast<unsigned long long&>(d))
        : "l"(reinterpret_cast<const unsigned long long&>(a)),
          "l"(reinterpret_cast<const unsigned long long&>(b)));
}

// One degree-group step (both nets, RPW=4 rows).
// Lane l owns cols 64e+2l+{0,1}, e in [E0,4). CNT = group size, E0 = off>>6.
template<int CNT, int E0>
__device__ __forceinline__ void do_step(
    int l, int off, const float2 y2[RPW],
    float2 a0[2][RPW][4], float2 a1[2][RPW][4], float2 aout2[2][2],
    const float* SB,
    float2 (*sH0)[9][RPW], float2 (*sH1)[9][2])
{
    // ---- layer 0: a0 += y_j * W0row ----
#pragma unroll
    for (int net = 0; net < 2; net++) {
#pragma unroll
        for (int e = E0; e < 4; e++) {
            float2 wv = *(const float2*)(SB + net * 256 + 64 * e + 2 * l);
#pragma unroll
            for (int r = 0; r < RPW; r++) ffma2(a0[net][r][e], wv, y2[r]);
        }
    }
    // finalize h0 group [off, off+CNT) -> sH0[net][u][r] = {h,h}
#pragma unroll
    for (int net = 0; net < 2; net++) {
#pragma unroll
        for (int e = E0; e < 4; e++) {
            int u0 = 64 * e + 2 * l - off;
            if (u0 >= 0 && u0 < CNT) {
#pragma unroll
                for (int r = 0; r < RPW; r++) {
                    float h = fmaxf(a0[net][r][e].x, 0.f);
                    sH0[net][u0][r] = make_float2(h, h);
                }
            }
            if (u0 + 1 >= 0 && u0 + 1 < CNT) {
#pragma unroll
                for (int r = 0; r < RPW; r++) {
                    float h = fmaxf(a0[net][r][e].y, 0.f);
                    sH0[net][u0 + 1][r] = make_float2(h, h);
                }
            }
        }
    }
    __syncwarp();

    // ---- layer 1: a1 += h0_group @ W1 rows ----
#pragma unroll
    for (int u = 0; u < CNT; u++) {
#pragma unroll
        for (int net = 0; net < 2; net++) {
            const float* wr = SB + W1OFF + (net * 9 + u) * 256;
            float2 wv[4];
#pragma unroll
            for (int e = E0; e < 4; e++)
                wv[e] = *(const float2*)(wr + 64 * e + 2 * l);
            float4 hq0 = *(const float4*)&sH0[net][u][0];  // {h0,h0,h1,h1}
            float4 hq1 = *(const float4*)&sH0[net][u][2];  // {h2,h2,h3,h3}
            float2 h0 = make_float2(hq0.x, hq0.y);
            float2 h1 = make_float2(hq0.z, hq0.w);
            float2 h2 = make_float2(hq1.x, hq1.y);
            float2 h3 = make_float2(hq1.z, hq1.w);
#pragma unroll
            for (int e = E0; e < 4; e++) {
                ffma2(a1[net][0][e], wv[e], h0);
                ffma2(a1[net][1][e], wv[e], h1);
                ffma2(a1[net][2][e], wv[e], h2);
                ffma2(a1[net][3][e], wv[e], h3);
            }
        }
    }
    // finalize h1 group -> sH1[net][u][rp] = {h(2rp), h(2rp+1)}
#pragma unroll
    for (int net = 0; net < 2; net++) {
#pragma unroll
        for (int e = E0; e < 4; e++) {
            int u0 = 64 * e + 2 * l - off;
            if (u0 >= 0 && u0 < CNT) {
#pragma unroll
                for (int rp = 0; rp < 2; rp++)
                    sH1[net][u0][rp] = make_float2(
                        fmaxf(a1[net][2 * rp][e].x, 0.f),
                        fmaxf(a1[net][2 * rp + 1][e].x, 0.f));
            }
            if (u0 + 1 >= 0 && u0 + 1 < CNT) {
#pragma unroll
                for (int rp = 0; rp < 2; rp++)
                    sH1[net][u0 + 1][rp] = make_float2(
                        fmaxf(a1[net][2 * rp][e].y, 0.f),
                        fmaxf(a1[net][2 * rp + 1][e].y, 0.f));
            }
        }
    }
    __syncwarp();

    // ---- layer 2: aout += h1_group @ W2 rows (row-pair packed) ----
#pragma unroll
    for (int u = 0; u < CNT; u++) {
#pragma unroll
        for (int net = 0; net < 2; net++) {
            float wf = SB[W2OFF + (net * 9 + u) * 32 + l];
            float2 w2 = make_float2(wf, wf);
#pragma unroll
            for (int rp = 0; rp < 2; rp++) {
                float2 h2 = sH1[net][u][rp];
                ffma2(aout2[net][rp], h2, w2);
            }
        }
    }
}

// Prefetch weights for a step (row j, group offset off) into step slot SB.
// Warp-structured: shift/add indexing only (no div/mod).
//   warps 0,1: W0 row (net = w); warps 2,3: W2 rows (net = w-2);
//   all warps: W1 row-slices round-robin (s = w + 4i).
template<int CNT, int E0>
__device__ __forceinline__ void prefetch_step(
    int j, int off, int tid, float* SB)
{
    constexpr int KC = 64 - 16 * E0;   // 16B chunks per W0/W1 row
    const int w = tid >> 5;
    const int l = tid & 31;

    if (w < 2) {
        // W0 row j, net = w
#pragma unroll
        for (int k = 0; k < 2; k++) {
            int q = l + 32 * k;
            if (q < KC)
                cp16(SB + w * 256 + 64 * E0 + 4 * q,
                     &g_W0p[w][j][64 * E0 + 4 * q]);
        }
    } else {
        // W2 rows, net = w - 2: CNT*8 chunks (<= 72), lanes cover 32 each
        int net = w - 2;
#pragma unroll
        for (int m = 0; m < 3; m++) {
            int idx = l + 32 * m;
            if (idx < CNT * 8) {
                int u = idx >> 3, q = idx & 7;
                cp16(SB + W2OFF + (net * 9 + u) * 32 + 4 * q,
                     &g_W2p[net][off + u][4 * q]);
            }
        }
    }

    // W1: 2*CNT row-slices over 4 warps
#pragma unroll
    for (int i = 0; i < 5; i++) {
        int s = w + 4 * i;
        if (s < 2 * CNT) {
            int net = (s >= CNT) ? 1 : 0;
            int u = net ? (s - CNT) : s;
#pragma unroll
            for (int k = 0; k < 2; k++) {
                int q = l + 32 * k;
                if (q < KC)
                    cp16(SB + W1OFF + (net * 9 + u) * 256 + 64 * E0 + 4 * q,
                         &g_W1p[net][off + u][64 * E0 + 4 * q]);
            }
        }
    }
}

__device__ __forceinline__ void dispatch_prefetch(int t, int tid, float* SB) {
    const int j = t - 1;
    const int off = (t <= 9) ? 9 * (t - 1) : 72 + 8 * (t - 9);
    if (t <= 8)       prefetch_step<9, 0>(j, off, tid, SB);
    else if (t <= 15) prefetch_step<8, 1>(j, off, tid, SB);
    else if (t <= 23) prefetch_step<8, 2>(j, off, tid, SB);
    else              prefetch_step<8, 3>(j, off, tid, SB);
}

__global__ __launch_bounds__(THREADS, 2)
void afmade_kernel(const float* __restrict__ x, float* __restrict__ out)
{
    // dynamic smem: 4 step slots (2 phases x 2 steps) x STEP_FLOATS
    extern __shared__ __align__(16) unsigned char dynsm[];
    float* SW = (float*)dynsm;

    __shared__ __align__(16) float2 sH0s[NWARP][2][9][RPW];  // per-warp h0 {h,h}
    __shared__ __align__(16) float2 sH1s[NWARP][2][9][2];    // per-warp h1 row pairs

    const int tid = threadIdx.x;
    const int w   = tid >> 5;
    const int l   = tid & 31;
    const int base_row = (blockIdx.x * NWARP + w) * RPW;

    float2 a0[2][RPW][4], a1[2][RPW][4], aout2[2][2];
    float2 xr2[2], lssum2[2];

#pragma unroll
    for (int net = 0; net < 2; net++) {
#pragma unroll
        for (int e = 0; e < 4; e++) {
            float2 b0v = *(const float2*)&g_b0p[net][64 * e + 2 * l];
            float2 b1v = *(const float2*)&g_b1p[net][64 * e + 2 * l];
#pragma unroll
            for (int r = 0; r < RPW; r++) { a0[net][r][e] = b0v; a1[net][r][e] = b1v; }
        }
        float b2v = g_b2[net][l];
        aout2[net][0] = make_float2(b2v, b2v);
        aout2[net][1] = make_float2(b2v, b2v);
    }
#pragma unroll
    for (int rp = 0; rp < 2; rp++) {
        lssum2[rp] = make_float2(0.f, 0.f);
        xr2[rp] = make_float2(x[(base_row + 2 * rp) * 32 + l],
                              x[(base_row + 2 * rp + 1) * 32 + l]);
    }

    // Prologue: stage phase 0 (steps 1, 2) into slots 0, 1.
    prefetch_step<9, 0>(0, 0, tid, SW);                 // t=1 -> slot 0
    prefetch_step<9, 0>(1, 9, tid, SW + STEP_FLOATS);   // t=2 -> slot 1
    cp_commit();

    for (int t = 1; t <= 32; ++t) {
        const int j = t - 1;
        // ---- emit coordinate j: y = (x - mu) * exp(-ls); ls = 0.5*lv ----
        // (eps dropped: exp(ls) >= ~0.05 so +1e-12 contributes <= 2e-11 rel)
        float2 y2[RPW];
#pragma unroll
        for (int rp = 0; rp < 2; rp++) {
            float nls0 = -0.5f * aout2[1][rp].x;
            float nls1 = -0.5f * aout2[1][rp].y;
            float yc0 = (xr2[rp].x - aout2[0][rp].x) * __expf(nls0);
            float yc1 = (xr2[rp].y - aout2[0][rp].y) * __expf(nls1);
            if (l == j) {
                lssum2[rp].x -= nls0;
                lssum2[rp].y -= nls1;
                out[(base_row + 2 * rp) * 32 + j]     = yc0;
                out[(base_row + 2 * rp + 1) * 32 + j] = yc1;
            }
            float yv0 = __shfl_sync(0xffffffffu, yc0, j);
            float yv1 = __shfl_sync(0xffffffffu, yc1, j);
            y2[2 * rp]     = make_float2(yv0, yv0);
            y2[2 * rp + 1] = make_float2(yv1, yv1);
        }
        if (t == 32) break;

        if (t & 1) {
            // Phase boundary: weights for steps t, t+1 must be resident.
            cp_wait_all();
            __syncthreads();
            // Prefetch next phase into the slots freed by the previous one.
            if (t + 2 <= 31) {
                const int pn = (t + 1) >> 1;   // next phase index
                float* NB = SW + ((pn & 1) * 2) * STEP_FLOATS;
                dispatch_prefetch(t + 2, tid, NB);
                if (t + 3 <= 31)
                    dispatch_prefetch(t + 3, tid, NB + STEP_FLOATS);
                cp_commit();
            }
        }
        // even t: no cross-warp sync — warps free-run within the phase

        const int off = (t <= 9) ? 9 * (t - 1) : 72 + 8 * (t - 9);
        const float* SB = SW + ((((t - 1) >> 1) & 1) * 2 + ((t - 1) & 1)) * STEP_FLOATS;
        if (t <= 8)
            do_step<9, 0>(l, off, y2, a0, a1, aout2, SB, sH0s[w], sH1s[w]);
        else if (t <= 15)
            do_step<8, 1>(l, off, y2, a0, a1, aout2, SB, sH0s[w], sH1s[w]);
        else if (t <= 23)
            do_step<8, 2>(l, off, y2, a0, a1, aout2, SB, sH0s[w], sH1s[w]);
        else
            do_step<8, 3>(l, off, y2, a0, a1, aout2, SB, sH0s[w], sH1s[w]);
    }

    // ---- logstd row-sums (lane l holds coordinate l's contribution) ----
#pragma unroll
    for (int rp = 0; rp < 2; rp++) {
        float sx = lssum2[rp].x, sy = lssum2[rp].y;
#pragma unroll
        for (int o = 16; o > 0; o >>= 1) {
            sx += __shfl_xor_sync(0xffffffffu, sx, o);
            sy += __shfl_xor_sync(0xffffffffu, sy, o);
        }
        if (l == 0) {
            out[Bb * Dd + base_row + 2 * rp]     = sx;
            out[Bb * Dd + base_row + 2 * rp + 1] = sy;
        }
    }
}

extern "C" void kernel_launch(void* const* d_in, const int* in_sizes, int n_in,
                              void* d_out, int out_size)
{
    (void)in_sizes; (void)n_in; (void)out_size;
    const float* x = (const float*)d_in[0];

    prep_kernel<<<512, 256>>>(
        (const float*)d_in[1],  (const float*)d_in[2],  (const float*)d_in[3],
        (const float*)d_in[4],  (const float*)d_in[5],  (const float*)d_in[6],
        (const float*)d_in[7],  (const float*)d_in[8],  (const float*)d_in[9],
        (const float*)d_in[10], (const float*)d_in[11], (const float*)d_in[12]);

    const int dyn_smem = 4 * STEP_FLOATS * 4;   // 91136 B (4 step slots)
    cudaFuncSetAttribute(afmade_kernel,
                         cudaFuncAttributeMaxDynamicSharedMemorySize, dyn_smem);
    afmade_kernel<<<GRID, THREADS, dyn_smem>>>(x, (float*)d_out);
}

// round 13
// speedup vs baseline: 1.3058x; 1.0255x over previous
#include <cuda_runtime.h>
#include <cstdint>
#include <math.h>

// AFMADEBlock: incremental triangular evaluation of the MADE autoregressive
// inverse. One degree-group finalized per step (31 steps).
//
// R13 = R12 + segment-split main loop. The t-loop is split into 4 sequential
// loops with compile-time (CNT,E0), so accumulator registers of finalized
// 64-col blocks (a0/a1[..][e<E0]) go DEAD at segment boundaries -> ptxas
// reclaims up to 96 regs in later segments for load pipelining (regs=255
// left zero slack; layer-1 LDS chains were exposed, issue stuck at 43%).

#define Dd 32
#define Bb 4096
#define RPW 4                  // rows per warp
#define NWARP 4                // warps per block
#define THREADS (NWARP * 32)   // 128
#define ROWS_PER_BLOCK (NWARP * RPW)   // 16
#define GRID (Bb / ROWS_PER_BLOCK)     // 256

#define STEP_FLOATS 5696       // per-step staged weights (2 nets)
#define W1OFF 512
#define W2OFF 5120

// Permuted+masked weights (hidden units sorted by degree). ~656KB, static.
__device__ __align__(16) float g_W0p[2][32][256];
__device__ __align__(16) float g_W1p[2][256][256];
__device__ __align__(16) float g_W2p[2][256][32];
__device__ __align__(16) float g_b0p[2][256];
__device__ __align__(16) float g_b1p[2][256];
__device__ __align__(16) float g_b2[2][32];

// deg(i) = (i % 31) + 1 for original hidden index i.
// Sorted order: degrees 1..8 have 9 units, degrees 9..31 have 8 units.
__device__ __forceinline__ int degS(int k) {
    return (k < 72) ? (k / 9 + 1) : ((k - 72) / 8 + 9);
}
__device__ __forceinline__ int permS(int k) {
    int d, jj;
    if (k < 72) { d = k / 9 + 1;        jj = k % 9; }
    else        { d = (k - 72) / 8 + 9; jj = (k - 72) % 8; }
    return (d - 1) + 31 * jj;   // original index of k-th sorted unit
}

__global__ void prep_kernel(
    const float* __restrict__ mu_W0, const float* __restrict__ mu_b0,
    const float* __restrict__ mu_W1, const float* __restrict__ mu_b1,
    const float* __restrict__ mu_W2, const float* __restrict__ mu_b2,
    const float* __restrict__ lv_W0, const float* __restrict__ lv_b0,
    const float* __restrict__ lv_W1, const float* __restrict__ lv_b1,
    const float* __restrict__ lv_W2, const float* __restrict__ lv_b2)
{
    int idx = blockIdx.x * blockDim.x + threadIdx.x;
    if (idx >= 2 * 256 * 256) return;
    int net = idx >> 16;
    int k   = (idx >> 8) & 255;   // sorted hidden row
    int c   = idx & 255;          // sorted hidden col

    const float* W0 = net ? lv_W0 : mu_W0;
    const float* b0 = net ? lv_b0 : mu_b0;
    const float* W1 = net ? lv_W1 : mu_W1;
    const float* b1 = net ? lv_b1 : mu_b1;
    const float* W2 = net ? lv_W2 : mu_W2;
    const float* b2 = net ? lv_b2 : mu_b2;

    int dk = degS(k), pk = permS(k);
    int dc = degS(c), pc = permS(c);

    g_W1p[net][k][c] = (dc >= dk) ? W1[pk * 256 + pc] : 0.f;
    if (k < 32) g_W0p[net][k][c] = (dc >= (k + 1)) ? W0[k * 256 + pc] : 0.f;
    if (c < 32) g_W2p[net][k][c] = ((c + 1) > dk) ? W2[pk * 32 + c] : 0.f;
    if (k == 0) {
        g_b0p[net][c] = b0[pc];
        g_b1p[net][c] = b1[pc];
        if (c < 32) g_b2[net][c] = b2[c];
    }
}

__device__ __forceinline__ void cp16(void* s, const void* g) {
    unsigned int sa = (unsigned int)__cvta_generic_to_shared(s);
    asm volatile("cp.async.cg.shared.global [%0], [%1], 16;" :: "r"(sa), "l"(g));
}
__device__ __forceinline__ void cp_commit() {
    asm volatile("cp.async.commit_group;");
}
__device__ __forceinline__ void cp_wait_all() {
    asm volatile("cp.async.wait_group 0;");
}

// Packed dual-fp32 FMA: d = a*b + d (elementwise on the two f32 halves).
__device__ __forceinline__ void ffma2(float2& d, const float2& a, const float2& b) {
    asm("fma.rn.f32x2 %0, %1, %2, %0;"
        : "+l"(reinterpret_cast<unsigned long long&>(d))
        : "l"(reinterpret_cast<const unsigned long long&>(a)),
          "l"(reinterpret_cast<const unsigned long long&>(b)));
}

// One degree-group step (both nets, RPW=4 rows).
// Lane l owns cols 64e+2l+{0,1}, e in [E0,4). CNT = group size, E0 = off>>6.
template<int CNT, int E0>
__device__ __forceinline__ void do_step(
    int l, int off, const float2 y2[RPW],
    float2 a0[2][RPW][4], float2 a1[2][RPW][4], float2 aout2[2][2],
    const float* SB,
    float2 (*sH0)[9][RPW], float2 (*sH1)[9][2])
{
    // ---- layer 0: a0 += y_j * W0row ----
#pragma unroll
    for (int net = 0; net < 2; net++) {
#pragma unroll
        for (int e = E0; e < 4; e++) {
            float2 wv = *(const float2*)(SB + net * 256 + 64 * e + 2 * l);
#pragma unroll
            for (int r = 0; r < RPW; r++) ffma2(a0[net][r][e], wv, y2[r]);
        }
    }
    // finalize h0 group [off, off+CNT) -> sH0[net][u][r] = {h,h}
#pragma unroll
    for (int net = 0; net < 2; net++) {
#pragma unroll
        for (int e = E0; e < 4; e++) {
            int u0 = 64 * e + 2 * l - off;
            if (u0 >= 0 && u0 < CNT) {
#pragma unroll
                for (int r = 0; r < RPW; r++) {
                    float h = fmaxf(a0[net][r][e].x, 0.f);
                    sH0[net][u0][r] = make_float2(h, h);
                }
            }
            if (u0 + 1 >= 0 && u0 + 1 < CNT) {
#pragma unroll
                for (int r = 0; r < RPW; r++) {
                    float h = fmaxf(a0[net][r][e].y, 0.f);
                    sH0[net][u0 + 1][r] = make_float2(h, h);
                }
            }
        }
    }
    __syncwarp();

    // ---- layer 1: a1 += h0_group @ W1 rows ----
#pragma unroll
    for (int u = 0; u < CNT; u++) {
#pragma unroll
        for (int net = 0; net < 2; net++) {
            const float* wr = SB + W1OFF + (net * 9 + u) * 256;
            float2 wv[4];
#pragma unroll
            for (int e = E0; e < 4; e++)
                wv[e] = *(const float2*)(wr + 64 * e + 2 * l);
            float4 hq0 = *(const float4*)&sH0[net][u][0];  // {h0,h0,h1,h1}
            float4 hq1 = *(const float4*)&sH0[net][u][2];  // {h2,h2,h3,h3}
            float2 h0 = make_float2(hq0.x, hq0.y);
            float2 h1 = make_float2(hq0.z, hq0.w);
            float2 h2 = make_float2(hq1.x, hq1.y);
            float2 h3 = make_float2(hq1.z, hq1.w);
#pragma unroll
            for (int e = E0; e < 4; e++) {
                ffma2(a1[net][0][e], wv[e], h0);
                ffma2(a1[net][1][e], wv[e], h1);
                ffma2(a1[net][2][e], wv[e], h2);
                ffma2(a1[net][3][e], wv[e], h3);
            }
        }
    }
    // finalize h1 group -> sH1[net][u][rp] = {h(2rp), h(2rp+1)}
#pragma unroll
    for (int net = 0; net < 2; net++) {
#pragma unroll
        for (int e = E0; e < 4; e++) {
            int u0 = 64 * e + 2 * l - off;
            if (u0 >= 0 && u0 < CNT) {
#pragma unroll
                for (int rp = 0; rp < 2; rp++)
                    sH1[net][u0][rp] = make_float2(
                        fmaxf(a1[net][2 * rp][e].x, 0.f),
                        fmaxf(a1[net][2 * rp + 1][e].x, 0.f));
            }
            if (u0 + 1 >= 0 && u0 + 1 < CNT) {
#pragma unroll
                for (int rp = 0; rp < 2; rp++)
                    sH1[net][u0 + 1][rp] = make_float2(
                        fmaxf(a1[net][2 * rp][e].y, 0.f),
                        fmaxf(a1[net][2 * rp + 1][e].y, 0.f));
            }
        }
    }
    __syncwarp();

    // ---- layer 2: aout += h1_group @ W2 rows (row-pair packed) ----
#pragma unroll
    for (int u = 0; u < CNT; u++) {
#pragma unroll
        for (int net = 0; net < 2; net++) {
            float wf = SB[W2OFF + (net * 9 + u) * 32 + l];
            float2 w2 = make_float2(wf, wf);
#pragma unroll
            for (int rp = 0; rp < 2; rp++) {
                float2 h2 = sH1[net][u][rp];
                ffma2(aout2[net][rp], h2, w2);
            }
        }
    }
}

// Prefetch weights for a step (row j, group offset off) into step slot SB.
// Warp-structured: shift/add indexing only (no div/mod).
template<int CNT, int E0>
__device__ __forceinline__ void prefetch_step(
    int j, int off, int tid, float* SB)
{
    constexpr int KC = 64 - 16 * E0;   // 16B chunks per W0/W1 row
    const int w = tid >> 5;
    const int l = tid & 31;

    if (w < 2) {
        // W0 row j, net = w
#pragma unroll
        for (int k = 0; k < 2; k++) {
            int q = l + 32 * k;
            if (q < KC)
                cp16(SB + w * 256 + 64 * E0 + 4 * q,
                     &g_W0p[w][j][64 * E0 + 4 * q]);
        }
    } else {
        // W2 rows, net = w - 2: CNT*8 chunks (<= 72), lanes cover 32 each
        int net = w - 2;
#pragma unroll
        for (int m = 0; m < 3; m++) {
            int idx = l + 32 * m;
            if (idx < CNT * 8) {
                int u = idx >> 3, q = idx & 7;
                cp16(SB + W2OFF + (net * 9 + u) * 32 + 4 * q,
                     &g_W2p[net][off + u][4 * q]);
            }
        }
    }

    // W1: 2*CNT row-slices over 4 warps
#pragma unroll
    for (int i = 0; i < 5; i++) {
        int s = w + 4 * i;
        if (s < 2 * CNT) {
            int net = (s >= CNT) ? 1 : 0;
            int u = net ? (s - CNT) : s;
#pragma unroll
            for (int k = 0; k < 2; k++) {
                int q = l + 32 * k;
                if (q < KC)
                    cp16(SB + W1OFF + (net * 9 + u) * 256 + 64 * E0 + 4 * q,
                         &g_W1p[net][off + u][64 * E0 + 4 * q]);
            }
        }
    }
}

__device__ __forceinline__ void dispatch_prefetch(int t, int tid, float* SB) {
    const int j = t - 1;
    const int off = (t <= 9) ? 9 * (t - 1) : 72 + 8 * (t - 9);
    if (t <= 8)       prefetch_step<9, 0>(j, off, tid, SB);
    else if (t <= 15) prefetch_step<8, 1>(j, off, tid, SB);
    else if (t <= 23) prefetch_step<8, 2>(j, off, tid, SB);
    else              prefetch_step<8, 3>(j, off, tid, SB);
}

// One segment of steps [t0, t1] with compile-time (CNT, E0). Splitting the
// main loop this way makes a0/a1[..][e<E0] dead in later segments, so
// ptxas reclaims their registers for load pipelining.
template<int CNT, int E0>
__device__ __forceinline__ void run_segment(
    int t0, int t1, int l, int tid, int base_row,
    const float2 xr2[2], float2 lssum2[2],
    float2 a0[2][RPW][4], float2 a1[2][RPW][4], float2 aout2[2][2],
    float* SW, float2 (*sH0)[9][RPW], float2 (*sH1)[9][2],
    float* __restrict__ out)
{
    for (int t = t0; t <= t1; ++t) {
        const int j = t - 1;
        // ---- emit coordinate j: y = (x - mu) * exp(-ls); ls = 0.5*lv ----
        float2 y2[RPW];
#pragma unroll
        for (int rp = 0; rp < 2; rp++) {
            float nls0 = -0.5f * aout2[1][rp].x;
            float nls1 = -0.5f * aout2[1][rp].y;
            float yc0 = (xr2[rp].x - aout2[0][rp].x) * __expf(nls0);
            float yc1 = (xr2[rp].y - aout2[0][rp].y) * __expf(nls1);
            if (l == j) {
                lssum2[rp].x -= nls0;
                lssum2[rp].y -= nls1;
                out[(base_row + 2 * rp) * 32 + j]     = yc0;
                out[(base_row + 2 * rp + 1) * 32 + j] = yc1;
            }
            float yv0 = __shfl_sync(0xffffffffu, yc0, j);
            float yv1 = __shfl_sync(0xffffffffu, yc1, j);
            y2[2 * rp]     = make_float2(yv0, yv0);
            y2[2 * rp + 1] = make_float2(yv1, yv1);
        }

        if (t & 1) {
            // Phase boundary: weights for steps t, t+1 must be resident.
            cp_wait_all();
            __syncthreads();
            // Prefetch next phase into the slots freed by the previous one.
            if (t + 2 <= 31) {
                const int pn = (t + 1) >> 1;   // next phase index
                float* NB = SW + ((pn & 1) * 2) * STEP_FLOATS;
                dispatch_prefetch(t + 2, tid, NB);
                if (t + 3 <= 31)
                    dispatch_prefetch(t + 3, tid, NB + STEP_FLOATS);
                cp_commit();
            }
        }
        // even t: no cross-warp sync — warps free-run within the phase

        const int off = (t <= 9) ? 9 * (t - 1) : 72 + 8 * (t - 9);
        const float* SB = SW + ((((t - 1) >> 1) & 1) * 2 + ((t - 1) & 1)) * STEP_FLOATS;
        do_step<CNT, E0>(l, off, y2, a0, a1, aout2, SB, sH0, sH1);
    }
}

__global__ __launch_bounds__(THREADS, 2)
void afmade_kernel(const float* __restrict__ x, float* __restrict__ out)
{
    // dynamic smem: 4 step slots (2 phases x 2 steps) x STEP_FLOATS
    extern __shared__ __align__(16) unsigned char dynsm[];
    float* SW = (float*)dynsm;

    __shared__ __align__(16) float2 sH0s[NWARP][2][9][RPW];  // per-warp h0 {h,h}
    __shared__ __align__(16) float2 sH1s[NWARP][2][9][2];    // per-warp h1 row pairs

    const int tid = threadIdx.x;
    const int w   = tid >> 5;
    const int l   = tid & 31;
    const int base_row = (blockIdx.x * NWARP + w) * RPW;

    float2 a0[2][RPW][4], a1[2][RPW][4], aout2[2][2];
    float2 xr2[2], lssum2[2];

#pragma unroll
    for (int net = 0; net < 2; net++) {
#pragma unroll
        for (int e = 0; e < 4; e++) {
            float2 b0v = *(const float2*)&g_b0p[net][64 * e + 2 * l];
            float2 b1v = *(const float2*)&g_b1p[net][64 * e + 2 * l];
#pragma unroll
            for (int r = 0; r < RPW; r++) { a0[net][r][e] = b0v; a1[net][r][e] = b1v; }
        }
        float b2v = g_b2[net][l];
        aout2[net][0] = make_float2(b2v, b2v);
        aout2[net][1] = make_float2(b2v, b2v);
    }
#pragma unroll
    for (int rp = 0; rp < 2; rp++) {
        lssum2[rp] = make_float2(0.f, 0.f);
        xr2[rp] = make_float2(x[(base_row + 2 * rp) * 32 + l],
                              x[(base_row + 2 * rp + 1) * 32 + l]);
    }

    // Prologue: stage phase 0 (steps 1, 2) into slots 0, 1.
    prefetch_step<9, 0>(0, 0, tid, SW);                 // t=1 -> slot 0
    prefetch_step<9, 0>(1, 9, tid, SW + STEP_FLOATS);   // t=2 -> slot 1
    cp_commit();

    // ---- 4 segments with compile-time (CNT, E0); dead accumulators of
    //      finalized 64-col blocks free registers at each boundary ----
    run_segment<9, 0>( 1,  8, l, tid, base_row, xr2, lssum2, a0, a1, aout2,
                       SW, sH0s[w], sH1s[w], out);
    run_segment<8, 1>( 9, 15, l, tid, base_row, xr2, lssum2, a0, a1, aout2,
                       SW, sH0s[w], sH1s[w], out);
    run_segment<8, 2>(16, 23, l, tid, base_row, xr2, lssum2, a0, a1, aout2,
                       SW, sH0s[w], sH1s[w], out);
    run_segment<8, 3>(24, 31, l, tid, base_row, xr2, lssum2, a0, a1, aout2,
                       SW, sH0s[w], sH1s[w], out);

    // ---- final emit (t = 32, j = 31) ----
    {
        const int j = 31;
#pragma unroll
        for (int rp = 0; rp < 2; rp++) {
            float nls0 = -0.5f * aout2[1][rp].x;
            float nls1 = -0.5f * aout2[1][rp].y;
            float yc0 = (xr2[rp].x - aout2[0][rp].x) * __expf(nls0);
            float yc1 = (xr2[rp].y - aout2[0][rp].y) * __expf(nls1);
            if (l == j) {
                lssum2[rp].x -= nls0;
                lssum2[rp].y -= nls1;
                out[(base_row + 2 * rp) * 32 + j]     = yc0;
                out[(base_row + 2 * rp + 1) * 32 + j] = yc1;
            }
        }
    }

    // ---- logstd row-sums (lane l holds coordinate l's contribution) ----
#pragma unroll
    for (int rp = 0; rp < 2; rp++) {
        float sx = lssum2[rp].x, sy = lssum2[rp].y;
#pragma unroll
        for (int o = 16; o > 0; o >>= 1) {
            sx += __shfl_xor_sync(0xffffffffu, sx, o);
            sy += __shfl_xor_sync(0xffffffffu, sy, o);
        }
        if (l == 0) {
            out[Bb * Dd + base_row + 2 * rp]     = sx;
            out[Bb * Dd + base_row + 2 * rp + 1] = sy;
        }
    }
}

extern "C" void kernel_launch(void* const* d_in, const int* in_sizes, int n_in,
                              void* d_out, int out_size)
{
    (void)in_sizes; (void)n_in; (void)out_size;
    const float* x = (const float*)d_in[0];

    prep_kernel<<<512, 256>>>(
        (const float*)d_in[1],  (const float*)d_in[2],  (const float*)d_in[3],
        (const float*)d_in[4],  (const float*)d_in[5],  (const float*)d_in[6],
        (const float*)d_in[7],  (const float*)d_in[8],  (const float*)d_in[9],
        (const float*)d_in[10], (const float*)d_in[11], (const float*)d_in[12]);

    const int dyn_smem = 4 * STEP_FLOATS * 4;   // 91136 B (4 step slots)
    cudaFuncSetAttribute(afmade_kernel,
                         cudaFuncAttributeMaxDynamicSharedMemorySize, dyn_smem);
    afmade_kernel<<<GRID, THREADS, dyn_smem>>>(x, (float*)d_out);
}

// round 14
// speedup vs baseline: 1.3568x; 1.0391x over previous
#include <cuda_runtime.h>
#include <cstdint>
#include <math.h>

// AFMADEBlock: incremental triangular evaluation of the MADE autoregressive
// inverse. One degree-group finalized per step (31 steps).
//
// R14 = R13 + warp-specialized producer + full-chip balance.
//  - grid 147, one 256-thr block per SM: warps 0-6 compute (28 rows/block,
//    critical-path rows/SM 32 -> 28), warp 7 = dedicated cp.async producer.
//  - compute warps lose ALL prefetch/addressing work (part of alu=20%).
//  - one explicit bar.sync(0,256) per phase (16 total), divergence-safe.
//  Everything else (segment split, dead-block skip, ffma2, 4-slot ring,
//  emit via exp(-ls)) identical to R13.

#define Dd 32
#define Bb 4096
#define RPW 4                  // rows per compute warp
#define NCW 7                  // compute warps per block
#define THREADS 256            // 7 compute + 1 producer warp
#define ROWS_PER_BLOCK (NCW * RPW)   // 28
#define GRID 147               // 147*28 = 4116 >= 4096

#define STEP_FLOATS 5696       // per-step staged weights (2 nets)
#define W1OFF 512
#define W2OFF 5120

// Permuted+masked weights (hidden units sorted by degree). ~656KB, static.
__device__ __align__(16) float g_W0p[2][32][256];
__device__ __align__(16) float g_W1p[2][256][256];
__device__ __align__(16) float g_W2p[2][256][32];
__device__ __align__(16) float g_b0p[2][256];
__device__ __align__(16) float g_b1p[2][256];
__device__ __align__(16) float g_b2[2][32];

__device__ __forceinline__ int degS(int k) {
    return (k < 72) ? (k / 9 + 1) : ((k - 72) / 8 + 9);
}
__device__ __forceinline__ int permS(int k) {
    int d, jj;
    if (k < 72) { d = k / 9 + 1;        jj = k % 9; }
    else        { d = (k - 72) / 8 + 9; jj = (k - 72) % 8; }
    return (d - 1) + 31 * jj;   // original index of k-th sorted unit
}

__global__ void prep_kernel(
    const float* __restrict__ mu_W0, const float* __restrict__ mu_b0,
    const float* __restrict__ mu_W1, const float* __restrict__ mu_b1,
    const float* __restrict__ mu_W2, const float* __restrict__ mu_b2,
    const float* __restrict__ lv_W0, const float* __restrict__ lv_b0,
    const float* __restrict__ lv_W1, const float* __restrict__ lv_b1,
    const float* __restrict__ lv_W2, const float* __restrict__ lv_b2)
{
    int idx = blockIdx.x * blockDim.x + threadIdx.x;
    if (idx >= 2 * 256 * 256) return;
    int net = idx >> 16;
    int k   = (idx >> 8) & 255;   // sorted hidden row
    int c   = idx & 255;          // sorted hidden col

    const float* W0 = net ? lv_W0 : mu_W0;
    const float* b0 = net ? lv_b0 : mu_b0;
    const float* W1 = net ? lv_W1 : mu_W1;
    const float* b1 = net ? lv_b1 : mu_b1;
    const float* W2 = net ? lv_W2 : mu_W2;
    const float* b2 = net ? lv_b2 : mu_b2;

    int dk = degS(k), pk = permS(k);
    int dc = degS(c), pc = permS(c);

    g_W1p[net][k][c] = (dc >= dk) ? W1[pk * 256 + pc] : 0.f;
    if (k < 32) g_W0p[net][k][c] = (dc >= (k + 1)) ? W0[k * 256 + pc] : 0.f;
    if (c < 32) g_W2p[net][k][c] = ((c + 1) > dk) ? W2[pk * 32 + c] : 0.f;
    if (k == 0) {
        g_b0p[net][c] = b0[pc];
        g_b1p[net][c] = b1[pc];
        if (c < 32) g_b2[net][c] = b2[c];
    }
}

__device__ __forceinline__ void cp16(void* s, const void* g) {
    unsigned int sa = (unsigned int)__cvta_generic_to_shared(s);
    asm volatile("cp.async.cg.shared.global [%0], [%1], 16;" :: "r"(sa), "l"(g));
}
__device__ __forceinline__ void cp_commit() {
    asm volatile("cp.async.commit_group;");
}
__device__ __forceinline__ void cp_wait_all() {
    asm volatile("cp.async.wait_group 0;");
}
// Explicit counted block barrier: legal from divergent call sites.
__device__ __forceinline__ void bar256() {
    asm volatile("bar.sync 0, 256;" ::: "memory");
}

// Packed dual-fp32 FMA: d = a*b + d (elementwise on the two f32 halves).
__device__ __forceinline__ void ffma2(float2& d, const float2& a, const float2& b) {
    asm("fma.rn.f32x2 %0, %1, %2, %0;"
        : "+l"(reinterpret_cast<unsigned long long&>(d))
        : "l"(reinterpret_cast<const unsigned long long&>(a)),
          "l"(reinterpret_cast<const unsigned long long&>(b)));
}

// One degree-group step (both nets, RPW=4 rows).
// Lane l owns cols 64e+2l+{0,1}, e in [E0,4). CNT = group size, E0 = off>>6.
template<int CNT, int E0>
__device__ __forceinline__ void do_step(
    int l, int off, const float2 y2[RPW],
    float2 a0[2][RPW][4], float2 a1[2][RPW][4], float2 aout2[2][2],
    const float* SB,
    float2 (*sH0)[9][RPW], float2 (*sH1)[9][2])
{
    // ---- layer 0: a0 += y_j * W0row ----
#pragma unroll
    for (int net = 0; net < 2; net++) {
#pragma unroll
        for (int e = E0; e < 4; e++) {
            float2 wv = *(const float2*)(SB + net * 256 + 64 * e + 2 * l);
#pragma unroll
            for (int r = 0; r < RPW; r++) ffma2(a0[net][r][e], wv, y2[r]);
        }
    }
    // finalize h0 group [off, off+CNT) -> sH0[net][u][r] = {h,h}
#pragma unroll
    for (int net = 0; net < 2; net++) {
#pragma unroll
        for (int e = E0; e < 4; e++) {
            int u0 = 64 * e + 2 * l - off;
            if (u0 >= 0 && u0 < CNT) {
#pragma unroll
                for (int r = 0; r < RPW; r++) {
                    float h = fmaxf(a0[net][r][e].x, 0.f);
                    sH0[net][u0][r] = make_float2(h, h);
                }
            }
            if (u0 + 1 >= 0 && u0 + 1 < CNT) {
#pragma unroll
                for (int r = 0; r < RPW; r++) {
                    float h = fmaxf(a0[net][r][e].y, 0.f);
                    sH0[net][u0 + 1][r] = make_float2(h, h);
                }
            }
        }
    }
    __syncwarp();

    // ---- layer 1: a1 += h0_group @ W1 rows ----
#pragma unroll
    for (int u = 0; u < CNT; u++) {
#pragma unroll
        for (int net = 0; net < 2; net++) {
            const float* wr = SB + W1OFF + (net * 9 + u) * 256;
            float2 wv[4];
#pragma unroll
            for (int e = E0; e < 4; e++)
                wv[e] = *(const float2*)(wr + 64 * e + 2 * l);
            float4 hq0 = *(const float4*)&sH0[net][u][0];  // {h0,h0,h1,h1}
            float4 hq1 = *(const float4*)&sH0[net][u][2];  // {h2,h2,h3,h3}
            float2 h0 = make_float2(hq0.x, hq0.y);
            float2 h1 = make_float2(hq0.z, hq0.w);
            float2 h2 = make_float2(hq1.x, hq1.y);
            float2 h3 = make_float2(hq1.z, hq1.w);
#pragma unroll
            for (int e = E0; e < 4; e++) {
                ffma2(a1[net][0][e], wv[e], h0);
                ffma2(a1[net][1][e], wv[e], h1);
                ffma2(a1[net][2][e], wv[e], h2);
                ffma2(a1[net][3][e], wv[e], h3);
            }
        }
    }
    // finalize h1 group -> sH1[net][u][rp] = {h(2rp), h(2rp+1)}
#pragma unroll
    for (int net = 0; net < 2; net++) {
#pragma unroll
        for (int e = E0; e < 4; e++) {
            int u0 = 64 * e + 2 * l - off;
            if (u0 >= 0 && u0 < CNT) {
#pragma unroll
                for (int rp = 0; rp < 2; rp++)
                    sH1[net][u0][rp] = make_float2(
                        fmaxf(a1[net][2 * rp][e].x, 0.f),
                        fmaxf(a1[net][2 * rp + 1][e].x, 0.f));
            }
            if (u0 + 1 >= 0 && u0 + 1 < CNT) {
#pragma unroll
                for (int rp = 0; rp < 2; rp++)
                    sH1[net][u0 + 1][rp] = make_float2(
                        fmaxf(a1[net][2 * rp][e].y, 0.f),
                        fmaxf(a1[net][2 * rp + 1][e].y, 0.f));
            }
        }
    }
    __syncwarp();

    // ---- layer 2: aout += h1_group @ W2 rows (row-pair packed) ----
#pragma unroll
    for (int u = 0; u < CNT; u++) {
#pragma unroll
        for (int net = 0; net < 2; net++) {
            float wf = SB[W2OFF + (net * 9 + u) * 32 + l];
            float2 w2 = make_float2(wf, wf);
#pragma unroll
            for (int rp = 0; rp < 2; rp++) {
                float2 h2 = sH1[net][u][rp];
                ffma2(aout2[net][rp], h2, w2);
            }
        }
    }
}

// Single-warp prefetch of one step's weights (producer warp only).
template<int CNT, int E0>
__device__ __forceinline__ void prefetch_step_1w(int j, int off, int l, float* SB)
{
    constexpr int KC = 64 - 16 * E0;   // 16B chunks per W0/W1 row
#pragma unroll
    for (int net = 0; net < 2; net++) {
        // W0 row j
#pragma unroll
        for (int k = 0; k < 2; k++) {
            int q = l + 32 * k;
            if (q < KC)
                cp16(SB + net * 256 + 64 * E0 + 4 * q,
                     &g_W0p[net][j][64 * E0 + 4 * q]);
        }
        // W1 rows off..off+CNT-1
#pragma unroll
        for (int u = 0; u < CNT; u++) {
#pragma unroll
            for (int k = 0; k < 2; k++) {
                int q = l + 32 * k;
                if (q < KC)
                    cp16(SB + W1OFF + (net * 9 + u) * 256 + 64 * E0 + 4 * q,
                         &g_W1p[net][off + u][64 * E0 + 4 * q]);
            }
        }
        // W2 rows: CNT*8 chunks (<= 72)
#pragma unroll
        for (int m = 0; m < 3; m++) {
            int idx = l + 32 * m;
            if (idx < CNT * 8) {
                int u = idx >> 3, q = idx & 7;
                cp16(SB + W2OFF + (net * 9 + u) * 32 + 4 * q,
                     &g_W2p[net][off + u][4 * q]);
            }
        }
    }
}

__device__ __forceinline__ void dispatch_prefetch_1w(int t, int l, float* SB) {
    const int j = t - 1;
    const int off = (t <= 9) ? 9 * (t - 1) : 72 + 8 * (t - 9);
    if (t <= 8)       prefetch_step_1w<9, 0>(j, off, l, SB);
    else if (t <= 15) prefetch_step_1w<8, 1>(j, off, l, SB);
    else if (t <= 23) prefetch_step_1w<8, 2>(j, off, l, SB);
    else              prefetch_step_1w<8, 3>(j, off, l, SB);
}

// One segment of steps [t0, t1] with compile-time (CNT, E0) — consumer side.
// Barrier at each odd t pairs with the producer's per-phase barrier.
template<int CNT, int E0>
__device__ __forceinline__ void run_segment(
    int t0, int t1, int l, int base_row, bool valid,
    const float2 xr2[2], float2 lssum2[2],
    float2 a0[2][RPW][4], float2 a1[2][RPW][4], float2 aout2[2][2],
    float* SW, float2 (*sH0)[9][RPW], float2 (*sH1)[9][2],
    float* __restrict__ out)
{
    for (int t = t0; t <= t1; ++t) {
        const int j = t - 1;
        // ---- emit coordinate j: y = (x - mu) * exp(-ls); ls = 0.5*lv ----
        float2 y2[RPW];
#pragma unroll
        for (int rp = 0; rp < 2; rp++) {
            float nls0 = -0.5f * aout2[1][rp].x;
            float nls1 = -0.5f * aout2[1][rp].y;
            float yc0 = (xr2[rp].x - aout2[0][rp].x) * __expf(nls0);
            float yc1 = (xr2[rp].y - aout2[0][rp].y) * __expf(nls1);
            if (l == j) {
                lssum2[rp].x -= nls0;
                lssum2[rp].y -= nls1;
                if (valid) {
                    out[(base_row + 2 * rp) * 32 + j]     = yc0;
                    out[(base_row + 2 * rp + 1) * 32 + j] = yc1;
                }
            }
            float yv0 = __shfl_sync(0xffffffffu, yc0, j);
            float yv1 = __shfl_sync(0xffffffffu, yc1, j);
            y2[2 * rp]     = make_float2(yv0, yv0);
            y2[2 * rp + 1] = make_float2(yv1, yv1);
        }

        if (t & 1) bar256();   // phase boundary: weights for t, t+1 resident

        const int off = (t <= 9) ? 9 * (t - 1) : 72 + 8 * (t - 9);
        const float* SB = SW + ((((t - 1) >> 1) & 1) * 2 + ((t - 1) & 1)) * STEP_FLOATS;
        do_step<CNT, E0>(l, off, y2, a0, a1, aout2, SB, sH0, sH1);
    }
}

__global__ __launch_bounds__(THREADS, 1)
void afmade_kernel(const float* __restrict__ x, float* __restrict__ out)
{
    // dynamic smem: 4 step slots (2 phases x 2 steps) x STEP_FLOATS
    extern __shared__ __align__(16) unsigned char dynsm[];
    float* SW = (float*)dynsm;

    __shared__ __align__(16) float2 sH0s[NCW][2][9][RPW];  // per-warp h0 {h,h}
    __shared__ __align__(16) float2 sH1s[NCW][2][9][2];    // per-warp h1 row pairs

    const int tid = threadIdx.x;
    const int w   = tid >> 5;
    const int l   = tid & 31;

    if (w == NCW) {
        // ================= producer warp =================
        // Stage phase 0 (steps 1, 2) into slots 0, 1.
        prefetch_step_1w<9, 0>(0, 0, l, SW);
        prefetch_step_1w<9, 0>(1, 9, l, SW + STEP_FLOATS);
        cp_commit();
        for (int p = 0; p < 16; ++p) {
            cp_wait_all();
            bar256();                      // phase p data visible to consumers
            if (p < 15) {
                // stage phase p+1 into the slots freed by phase p-1
                float* NB = SW + (((p + 1) & 1) * 2) * STEP_FLOATS;
                const int t0 = 2 * p + 3;  // first step of phase p+1
                dispatch_prefetch_1w(t0, l, NB);
                if (t0 + 1 <= 31)
                    dispatch_prefetch_1w(t0 + 1, l, NB + STEP_FLOATS);
                cp_commit();
            }
        }
        return;
    }

    // ================= compute warps =================
    const int base_row_raw = blockIdx.x * ROWS_PER_BLOCK + w * RPW;
    const bool valid = (base_row_raw + RPW) <= Bb;   // warp-uniform (Bb % 4 == 0)
    const int base_row = valid ? base_row_raw : 0;

    float2 a0[2][RPW][4], a1[2][RPW][4], aout2[2][2];
    float2 xr2[2], lssum2[2];

#pragma unroll
    for (int net = 0; net < 2; net++) {
#pragma unroll
        for (int e = 0; e < 4; e++) {
            float2 b0v = *(const float2*)&g_b0p[net][64 * e + 2 * l];
            float2 b1v = *(const float2*)&g_b1p[net][64 * e + 2 * l];
#pragma unroll
            for (int r = 0; r < RPW; r++) { a0[net][r][e] = b0v; a1[net][r][e] = b1v; }
        }
        float b2v = g_b2[net][l];
        aout2[net][0] = make_float2(b2v, b2v);
        aout2[net][1] = make_float2(b2v, b2v);
    }
#pragma unroll
    for (int rp = 0; rp < 2; rp++) {
        lssum2[rp] = make_float2(0.f, 0.f);
        xr2[rp] = make_float2(x[(base_row + 2 * rp) * 32 + l],
                              x[(base_row + 2 * rp + 1) * 32 + l]);
    }

    // ---- 4 segments with compile-time (CNT, E0) ----
    run_segment<9, 0>( 1,  8, l, base_row, valid, xr2, lssum2, a0, a1, aout2,
                       SW, sH0s[w], sH1s[w], out);
    run_segment<8, 1>( 9, 15, l, base_row, valid, xr2, lssum2, a0, a1, aout2,
                       SW, sH0s[w], sH1s[w], out);
    run_segment<8, 2>(16, 23, l, base_row, valid, xr2, lssum2, a0, a1, aout2,
                       SW, sH0s[w], sH1s[w], out);
    run_segment<8, 3>(24, 31, l, base_row, valid, xr2, lssum2, a0, a1, aout2,
                       SW, sH0s[w], sH1s[w], out);

    // ---- final emit (t = 32, j = 31) ----
    {
        const int j = 31;
#pragma unroll
        for (int rp = 0; rp < 2; rp++) {
            float nls0 = -0.5f * aout2[1][rp].x;
            float nls1 = -0.5f * aout2[1][rp].y;
            float yc0 = (xr2[rp].x - aout2[0][rp].x) * __expf(nls0);
            float yc1 = (xr2[rp].y - aout2[0][rp].y) * __expf(nls1);
            if (l == j) {
                lssum2[rp].x -= nls0;
                lssum2[rp].y -= nls1;
                if (valid) {
                    out[(base_row + 2 * rp) * 32 + j]     = yc0;
                    out[(base_row + 2 * rp + 1) * 32 + j] = yc1;
                }
            }
        }
    }

    // ---- logstd row-sums (lane l holds coordinate l's contribution) ----
#pragma unroll
    for (int rp = 0; rp < 2; rp++) {
        float sx = lssum2[rp].x, sy = lssum2[rp].y;
#pragma unroll
        for (int o = 16; o > 0; o >>= 1) {
            sx += __shfl_xor_sync(0xffffffffu, sx, o);
            sy += __shfl_xor_sync(0xffffffffu, sy, o);
        }
        if (l == 0 && valid) {
            out[Bb * Dd + base_row + 2 * rp]     = sx;
            out[Bb * Dd + base_row + 2 * rp + 1] = sy;
        }
    }
}

extern "C" void kernel_launch(void* const* d_in, const int* in_sizes, int n_in,
                              void* d_out, int out_size)
{
    (void)in_sizes; (void)n_in; (void)out_size;
    const float* x = (const float*)d_in[0];

    prep_kernel<<<512, 256>>>(
        (const float*)d_in[1],  (const float*)d_in[2],  (const float*)d_in[3],
        (const float*)d_in[4],  (const float*)d_in[5],  (const float*)d_in[6],
        (const float*)d_in[7],  (const float*)d_in[8],  (const float*)d_in[9],
        (const float*)d_in[10], (const float*)d_in[11], (const float*)d_in[12]);

    const int dyn_smem = 4 * STEP_FLOATS * 4;   // 91136 B (4 step slots)
    cudaFuncSetAttribute(afmade_kernel,
                         cudaFuncAttributeMaxDynamicSharedMemorySize, dyn_smem);
    afmade_kernel<<<GRID, THREADS, dyn_smem>>>(x, (float*)d_out);
}

// round 15
// speedup vs baseline: 1.4297x; 1.0537x over previous
#include <cuda_runtime.h>
#include <cstdint>
#include <math.h>

// AFMADEBlock: incremental triangular evaluation of the MADE autoregressive
// inverse. One degree-group finalized per step (31 steps).
//
// R15 = R14 + (1) fully deferred outputs: aout[col l] is final after step l
// (later degree groups have exactly-zero W2 entries for col l), so the loop
// emit computes y only for the warp broadcast; y stores (now coalesced) and
// the logstd reduction move to a single epilogue. (2) explicit double-
// buffered layer-1 pipelining in segments E0>=2, where 64+ dead accumulator
// regs pay for the prefetch buffers (MLP>=2 on the 29-cyc LDS chains).

#define Dd 32
#define Bb 4096
#define RPW 4                  // rows per compute warp
#define NCW 7                  // compute warps per block
#define THREADS 256            // 7 compute + 1 producer warp
#define ROWS_PER_BLOCK (NCW * RPW)   // 28
#define GRID 147               // 147*28 = 4116 >= 4096

#define STEP_FLOATS 5696       // per-step staged weights (2 nets)
#define W1OFF 512
#define W2OFF 5120

// Permuted+masked weights (hidden units sorted by degree). ~656KB, static.
__device__ __align__(16) float g_W0p[2][32][256];
__device__ __align__(16) float g_W1p[2][256][256];
__device__ __align__(16) float g_W2p[2][256][32];
__device__ __align__(16) float g_b0p[2][256];
__device__ __align__(16) float g_b1p[2][256];
__device__ __align__(16) float g_b2[2][32];

__device__ __forceinline__ int degS(int k) {
    return (k < 72) ? (k / 9 + 1) : ((k - 72) / 8 + 9);
}
__device__ __forceinline__ int permS(int k) {
    int d, jj;
    if (k < 72) { d = k / 9 + 1;        jj = k % 9; }
    else        { d = (k - 72) / 8 + 9; jj = (k - 72) % 8; }
    return (d - 1) + 31 * jj;   // original index of k-th sorted unit
}

__global__ void prep_kernel(
    const float* __restrict__ mu_W0, const float* __restrict__ mu_b0,
    const float* __restrict__ mu_W1, const float* __restrict__ mu_b1,
    const float* __restrict__ mu_W2, const float* __restrict__ mu_b2,
    const float* __restrict__ lv_W0, const float* __restrict__ lv_b0,
    const float* __restrict__ lv_W1, const float* __restrict__ lv_b1,
    const float* __restrict__ lv_W2, const float* __restrict__ lv_b2)
{
    int idx = blockIdx.x * blockDim.x + threadIdx.x;
    if (idx >= 2 * 256 * 256) return;
    int net = idx >> 16;
    int k   = (idx >> 8) & 255;   // sorted hidden row
    int c   = idx & 255;          // sorted hidden col

    const float* W0 = net ? lv_W0 : mu_W0;
    const float* b0 = net ? lv_b0 : mu_b0;
    const float* W1 = net ? lv_W1 : mu_W1;
    const float* b1 = net ? lv_b1 : mu_b1;
    const float* W2 = net ? lv_W2 : mu_W2;
    const float* b2 = net ? lv_b2 : mu_b2;

    int dk = degS(k), pk = permS(k);
    int dc = degS(c), pc = permS(c);

    g_W1p[net][k][c] = (dc >= dk) ? W1[pk * 256 + pc] : 0.f;
    if (k < 32) g_W0p[net][k][c] = (dc >= (k + 1)) ? W0[k * 256 + pc] : 0.f;
    if (c < 32) g_W2p[net][k][c] = ((c + 1) > dk) ? W2[pk * 32 + c] : 0.f;
    if (k == 0) {
        g_b0p[net][c] = b0[pc];
        g_b1p[net][c] = b1[pc];
        if (c < 32) g_b2[net][c] = b2[c];
    }
}

__device__ __forceinline__ void cp16(void* s, const void* g) {
    unsigned int sa = (unsigned int)__cvta_generic_to_shared(s);
    asm volatile("cp.async.cg.shared.global [%0], [%1], 16;" :: "r"(sa), "l"(g));
}
__device__ __forceinline__ void cp_commit() {
    asm volatile("cp.async.commit_group;");
}
__device__ __forceinline__ void cp_wait_all() {
    asm volatile("cp.async.wait_group 0;");
}
// Explicit counted block barrier: legal from divergent call sites.
__device__ __forceinline__ void bar256() {
    asm volatile("bar.sync 0, 256;" ::: "memory");
}

// Packed dual-fp32 FMA: d = a*b + d (elementwise on the two f32 halves).
__device__ __forceinline__ void ffma2(float2& d, const float2& a, const float2& b) {
    asm("fma.rn.f32x2 %0, %1, %2, %0;"
        : "+l"(reinterpret_cast<unsigned long long&>(d))
        : "l"(reinterpret_cast<const unsigned long long&>(a)),
          "l"(reinterpret_cast<const unsigned long long&>(b)));
}

// One degree-group step (both nets, RPW=4 rows).
// Lane l owns cols 64e+2l+{0,1}, e in [E0,4). CNT = group size, E0 = off>>6.
// PIPE: explicit double-buffered layer-1 load pipeline (use when regs free).
template<int CNT, int E0, bool PIPE>
__device__ __forceinline__ void do_step(
    int l, int off, const float2 y2[RPW],
    float2 a0[2][RPW][4], float2 a1[2][RPW][4], float2 aout2[2][2],
    const float* SB,
    float2 (*sH0)[9][RPW], float2 (*sH1)[9][2])
{
    // ---- layer 0: a0 += y_j * W0row ----
#pragma unroll
    for (int net = 0; net < 2; net++) {
#pragma unroll
        for (int e = E0; e < 4; e++) {
            float2 wv = *(const float2*)(SB + net * 256 + 64 * e + 2 * l);
#pragma unroll
            for (int r = 0; r < RPW; r++) ffma2(a0[net][r][e], wv, y2[r]);
        }
    }
    // finalize h0 group [off, off+CNT) -> sH0[net][u][r] = {h,h}
#pragma unroll
    for (int net = 0; net < 2; net++) {
#pragma unroll
        for (int e = E0; e < 4; e++) {
            int u0 = 64 * e + 2 * l - off;
            if (u0 >= 0 && u0 < CNT) {
#pragma unroll
                for (int r = 0; r < RPW; r++) {
                    float h = fmaxf(a0[net][r][e].x, 0.f);
                    sH0[net][u0][r] = make_float2(h, h);
                }
            }
            if (u0 + 1 >= 0 && u0 + 1 < CNT) {
#pragma unroll
                for (int r = 0; r < RPW; r++) {
                    float h = fmaxf(a0[net][r][e].y, 0.f);
                    sH0[net][u0 + 1][r] = make_float2(h, h);
                }
            }
        }
    }
    __syncwarp();

    // ---- layer 1: a1 += h0_group @ W1 rows ----
    if (PIPE) {
        // flatten (u, net): s = 2u + net; double-buffered loads
        float2 wv[2][4];
        float4 h01[2], h23[2];
        {
            const float* wr = SB + W1OFF;   // net 0, u 0
#pragma unroll
            for (int e = E0; e < 4; e++)
                wv[0][e] = *(const float2*)(wr + 64 * e + 2 * l);
            h01[0] = *(const float4*)&sH0[0][0][0];
            h23[0] = *(const float4*)&sH0[0][0][2];
        }
#pragma unroll
        for (int s = 0; s < 2 * CNT; s++) {
            const int cur = s & 1, nxt = cur ^ 1;
            if (s + 1 < 2 * CNT) {
                const int netn = (s + 1) & 1, un = (s + 1) >> 1;
                const float* wr = SB + W1OFF + (netn * 9 + un) * 256;
#pragma unroll
                for (int e = E0; e < 4; e++)
                    wv[nxt][e] = *(const float2*)(wr + 64 * e + 2 * l);
                h01[nxt] = *(const float4*)&sH0[netn][un][0];
                h23[nxt] = *(const float4*)&sH0[netn][un][2];
            }
            const int net = s & 1;
            float2 h0 = make_float2(h01[cur].x, h01[cur].y);
            float2 h1 = make_float2(h01[cur].z, h01[cur].w);
            float2 h2 = make_float2(h23[cur].x, h23[cur].y);
            float2 h3 = make_float2(h23[cur].z, h23[cur].w);
#pragma unroll
            for (int e = E0; e < 4; e++) {
                ffma2(a1[net][0][e], wv[cur][e], h0);
                ffma2(a1[net][1][e], wv[cur][e], h1);
                ffma2(a1[net][2][e], wv[cur][e], h2);
                ffma2(a1[net][3][e], wv[cur][e], h3);
            }
        }
    } else {
#pragma unroll
        for (int u = 0; u < CNT; u++) {
#pragma unroll
            for (int net = 0; net < 2; net++) {
                const float* wr = SB + W1OFF + (net * 9 + u) * 256;
                float2 wv[4];
#pragma unroll
                for (int e = E0; e < 4; e++)
                    wv[e] = *(const float2*)(wr + 64 * e + 2 * l);
                float4 hq0 = *(const float4*)&sH0[net][u][0];
                float4 hq1 = *(const float4*)&sH0[net][u][2];
                float2 h0 = make_float2(hq0.x, hq0.y);
                float2 h1 = make_float2(hq0.z, hq0.w);
                float2 h2 = make_float2(hq1.x, hq1.y);
                float2 h3 = make_float2(hq1.z, hq1.w);
#pragma unroll
                for (int e = E0; e < 4; e++) {
                    ffma2(a1[net][0][e], wv[e], h0);
                    ffma2(a1[net][1][e], wv[e], h1);
                    ffma2(a1[net][2][e], wv[e], h2);
                    ffma2(a1[net][3][e], wv[e], h3);
                }
            }
        }
    }
    // finalize h1 group -> sH1[net][u][rp] = {h(2rp), h(2rp+1)}
#pragma unroll
    for (int net = 0; net < 2; net++) {
#pragma unroll
        for (int e = E0; e < 4; e++) {
            int u0 = 64 * e + 2 * l - off;
            if (u0 >= 0 && u0 < CNT) {
#pragma unroll
                for (int rp = 0; rp < 2; rp++)
                    sH1[net][u0][rp] = make_float2(
                        fmaxf(a1[net][2 * rp][e].x, 0.f),
                        fmaxf(a1[net][2 * rp + 1][e].x, 0.f));
            }
            if (u0 + 1 >= 0 && u0 + 1 < CNT) {
#pragma unroll
                for (int rp = 0; rp < 2; rp++)
                    sH1[net][u0 + 1][rp] = make_float2(
                        fmaxf(a1[net][2 * rp][e].y, 0.f),
                        fmaxf(a1[net][2 * rp + 1][e].y, 0.f));
            }
        }
    }
    __syncwarp();

    // ---- layer 2: aout += h1_group @ W2 rows (row-pair packed) ----
#pragma unroll
    for (int u = 0; u < CNT; u++) {
#pragma unroll
        for (int net = 0; net < 2; net++) {
            float wf = SB[W2OFF + (net * 9 + u) * 32 + l];
            float2 w2 = make_float2(wf, wf);
#pragma unroll
            for (int rp = 0; rp < 2; rp++) {
                float2 h2 = sH1[net][u][rp];
                ffma2(aout2[net][rp], h2, w2);
            }
        }
    }
}

// Single-warp prefetch of one step's weights (producer warp only).
template<int CNT, int E0>
__device__ __forceinline__ void prefetch_step_1w(int j, int off, int l, float* SB)
{
    constexpr int KC = 64 - 16 * E0;   // 16B chunks per W0/W1 row
#pragma unroll
    for (int net = 0; net < 2; net++) {
#pragma unroll
        for (int k = 0; k < 2; k++) {
            int q = l + 32 * k;
            if (q < KC)
                cp16(SB + net * 256 + 64 * E0 + 4 * q,
                     &g_W0p[net][j][64 * E0 + 4 * q]);
        }
#pragma unroll
        for (int u = 0; u < CNT; u++) {
#pragma unroll
            for (int k = 0; k < 2; k++) {
                int q = l + 32 * k;
                if (q < KC)
                    cp16(SB + W1OFF + (net * 9 + u) * 256 + 64 * E0 + 4 * q,
                         &g_W1p[net][off + u][64 * E0 + 4 * q]);
            }
        }
#pragma unroll
        for (int m = 0; m < 3; m++) {
            int idx = l + 32 * m;
            if (idx < CNT * 8) {
                int u = idx >> 3, q = idx & 7;
                cp16(SB + W2OFF + (net * 9 + u) * 32 + 4 * q,
                     &g_W2p[net][off + u][4 * q]);
            }
        }
    }
}

__device__ __forceinline__ void dispatch_prefetch_1w(int t, int l, float* SB) {
    const int j = t - 1;
    const int off = (t <= 9) ? 9 * (t - 1) : 72 + 8 * (t - 9);
    if (t <= 8)       prefetch_step_1w<9, 0>(j, off, l, SB);
    else if (t <= 15) prefetch_step_1w<8, 1>(j, off, l, SB);
    else if (t <= 23) prefetch_step_1w<8, 2>(j, off, l, SB);
    else              prefetch_step_1w<8, 3>(j, off, l, SB);
}

// One segment of steps [t0, t1] with compile-time (CNT, E0) — consumer side.
// Emit computes y only for the broadcast; outputs are deferred to epilogue.
template<int CNT, int E0, bool PIPE>
__device__ __forceinline__ void run_segment(
    int t0, int t1, int l,
    const float2 xr2[2],
    float2 a0[2][RPW][4], float2 a1[2][RPW][4], float2 aout2[2][2],
    float* SW, float2 (*sH0)[9][RPW], float2 (*sH1)[9][2])
{
    for (int t = t0; t <= t1; ++t) {
        const int j = t - 1;
        // ---- broadcast y_j: y = (x - mu) * exp(-0.5*lv), lane j's value ----
        float2 y2[RPW];
#pragma unroll
        for (int rp = 0; rp < 2; rp++) {
            float nls0 = -0.5f * aout2[1][rp].x;
            float nls1 = -0.5f * aout2[1][rp].y;
            float yc0 = (xr2[rp].x - aout2[0][rp].x) * __expf(nls0);
            float yc1 = (xr2[rp].y - aout2[0][rp].y) * __expf(nls1);
            float yv0 = __shfl_sync(0xffffffffu, yc0, j);
            float yv1 = __shfl_sync(0xffffffffu, yc1, j);
            y2[2 * rp]     = make_float2(yv0, yv0);
            y2[2 * rp + 1] = make_float2(yv1, yv1);
        }

        if (t & 1) bar256();   // phase boundary: weights for t, t+1 resident

        const int off = (t <= 9) ? 9 * (t - 1) : 72 + 8 * (t - 9);
        const float* SB = SW + ((((t - 1) >> 1) & 1) * 2 + ((t - 1) & 1)) * STEP_FLOATS;
        do_step<CNT, E0, PIPE>(l, off, y2, a0, a1, aout2, SB, sH0, sH1);
    }
}

__global__ __launch_bounds__(THREADS, 1)
void afmade_kernel(const float* __restrict__ x, float* __restrict__ out)
{
    // dynamic smem: 4 step slots (2 phases x 2 steps) x STEP_FLOATS
    extern __shared__ __align__(16) unsigned char dynsm[];
    float* SW = (float*)dynsm;

    __shared__ __align__(16) float2 sH0s[NCW][2][9][RPW];  // per-warp h0 {h,h}
    __shared__ __align__(16) float2 sH1s[NCW][2][9][2];    // per-warp h1 row pairs

    const int tid = threadIdx.x;
    const int w   = tid >> 5;
    const int l   = tid & 31;

    if (w == NCW) {
        // ================= producer warp =================
        prefetch_step_1w<9, 0>(0, 0, l, SW);
        prefetch_step_1w<9, 0>(1, 9, l, SW + STEP_FLOATS);
        cp_commit();
        for (int p = 0; p < 16; ++p) {
            cp_wait_all();
            bar256();                      // phase p data visible to consumers
            if (p < 15) {
                float* NB = SW + (((p + 1) & 1) * 2) * STEP_FLOATS;
                const int t0 = 2 * p + 3;  // first step of phase p+1
                dispatch_prefetch_1w(t0, l, NB);
                if (t0 + 1 <= 31)
                    dispatch_prefetch_1w(t0 + 1, l, NB + STEP_FLOATS);
                cp_commit();
            }
        }
        return;
    }

    // ================= compute warps =================
    const int base_row_raw = blockIdx.x * ROWS_PER_BLOCK + w * RPW;
    const bool valid = (base_row_raw + RPW) <= Bb;   // warp-uniform
    const int base_row = valid ? base_row_raw : 0;

    float2 a0[2][RPW][4], a1[2][RPW][4], aout2[2][2];
    float2 xr2[2];

#pragma unroll
    for (int net = 0; net < 2; net++) {
#pragma unroll
        for (int e = 0; e < 4; e++) {
            float2 b0v = *(const float2*)&g_b0p[net][64 * e + 2 * l];
            float2 b1v = *(const float2*)&g_b1p[net][64 * e + 2 * l];
#pragma unroll
            for (int r = 0; r < RPW; r++) { a0[net][r][e] = b0v; a1[net][r][e] = b1v; }
        }
        float b2v = g_b2[net][l];
        aout2[net][0] = make_float2(b2v, b2v);
        aout2[net][1] = make_float2(b2v, b2v);
    }
#pragma unroll
    for (int rp = 0; rp < 2; rp++) {
        xr2[rp] = make_float2(x[(base_row + 2 * rp) * 32 + l],
                              x[(base_row + 2 * rp + 1) * 32 + l]);
    }

    // ---- 4 segments; PIPE in the two late segments (>=64 dead regs) ----
    run_segment<9, 0, false>( 1,  8, l, xr2, a0, a1, aout2, SW, sH0s[w], sH1s[w]);
    run_segment<8, 1, false>( 9, 15, l, xr2, a0, a1, aout2, SW, sH0s[w], sH1s[w]);
    run_segment<8, 2, true >(16, 23, l, xr2, a0, a1, aout2, SW, sH0s[w], sH1s[w]);
    run_segment<8, 3, true >(24, 31, l, xr2, a0, a1, aout2, SW, sH0s[w], sH1s[w]);

    // ---- epilogue: every col is final; emit y (coalesced) + logstd ----
    {
        float ls[RPW], yv[RPW];
#pragma unroll
        for (int rp = 0; rp < 2; rp++) {
            float nls0 = -0.5f * aout2[1][rp].x;
            float nls1 = -0.5f * aout2[1][rp].y;
            ls[2 * rp]     = -nls0;
            ls[2 * rp + 1] = -nls1;
            yv[2 * rp]     = (xr2[rp].x - aout2[0][rp].x) * __expf(nls0);
            yv[2 * rp + 1] = (xr2[rp].y - aout2[0][rp].y) * __expf(nls1);
        }
        if (valid) {
#pragma unroll
            for (int r = 0; r < RPW; r++)
                out[(base_row + r) * 32 + l] = yv[r];   // warp: 128B coalesced
        }
#pragma unroll
        for (int r = 0; r < RPW; r++) {
            float s = ls[r];
#pragma unroll
            for (int o = 16; o > 0; o >>= 1)
                s += __shfl_xor_sync(0xffffffffu, s, o);
            if (l == 0 && valid) out[Bb * Dd + base_row + r] = s;
        }
    }
}

extern "C" void kernel_launch(void* const* d_in, const int* in_sizes, int n_in,
                              void* d_out, int out_size)
{
    (void)in_sizes; (void)n_in; (void)out_size;
    const float* x = (const float*)d_in[0];

    prep_kernel<<<512, 256>>>(
        (const float*)d_in[1],  (const float*)d_in[2],  (const float*)d_in[3],
        (const float*)d_in[4],  (const float*)d_in[5],  (const float*)d_in[6],
        (const float*)d_in[7],  (const float*)d_in[8],  (const float*)d_in[9],
        (const float*)d_in[10], (const float*)d_in[11], (const float*)d_in[12]);

    const int dyn_smem = 4 * STEP_FLOATS * 4;   // 91136 B (4 step slots)
    cudaFuncSetAttribute(afmade_kernel,
                         cudaFuncAttributeMaxDynamicSharedMemorySize, dyn_smem);
    afmade_kernel<<<GRID, THREADS, dyn_smem>>>(x, (float*)d_out);
}